// round 11
// baseline (speedup 1.0000x reference)
#include <cuda_runtime.h>
#include <cstdint>

#define NB 16
#define NL 2048
#define NF 46
#define D_MODEL 256
#define D_INNER 512
#define D_STATE 64
#define NHEADS 8
#define HEADDIM 64
#define CONV_DIM 640
#define D_IN_PROJ 1160
#define N_LAYERS 4
#define BL (NB*NL)
#define CHUNK 64
#define NCHUNK (NL/CHUNK)

// ---------------- scratch (static device globals; no runtime allocation) ----
__device__ float g_h[(size_t)BL * D_MODEL];      // residual stream
__device__ float g_zx[(size_t)BL * D_IN_PROJ];   // in_proj output
__device__ float g_xc[(size_t)BL * CONV_DIM];    // conv+silu output (tf32-rounded)
__device__ float g_sd[(size_t)BL * NHEADS * 2];  // (dtA, dt) pairs, [b*8+h][l]
__device__ float g_y[(size_t)BL * D_INNER];      // scan output / gated-norm
__device__ float g_part[NB * 32 * D_MODEL];      // LN partial sums

// ---------------- tf32 / cp.async helpers ------------------------------------
__device__ __forceinline__ uint32_t to_tf32(float x) {
    uint32_t r;
    asm("cvt.rna.tf32.f32 %0, %1;" : "=r"(r) : "f"(x));
    return r;
}
__device__ __forceinline__ float tf32r(float x) {
    return __uint_as_float(to_tf32(x));
}
__device__ __forceinline__ void cpa16(void* dst, const void* src) {
    uint32_t d = (uint32_t)__cvta_generic_to_shared(dst);
    asm volatile("cp.async.cg.shared.global [%0], [%1], 16;" :: "r"(d), "l"(src));
}
__device__ __forceinline__ void cpa16z(void* dst, const void* src, int bytes) {
    uint32_t d = (uint32_t)__cvta_generic_to_shared(dst);
    asm volatile("cp.async.cg.shared.global [%0], [%1], 16, %2;"
                 :: "r"(d), "l"(src), "r"(bytes));
}
__device__ __forceinline__ void cpa_commit() { asm volatile("cp.async.commit_group;"); }
__device__ __forceinline__ void cpa_wait0()  { asm volatile("cp.async.wait_group 0;"); }
__device__ __forceinline__ void cpa_wait1()  { asm volatile("cp.async.wait_group 1;"); }

__device__ __forceinline__ void mma_tf32(float c[4], const uint32_t a[4], const uint32_t b[2]) {
    asm volatile(
        "mma.sync.aligned.m16n8k8.row.col.f32.tf32.tf32.f32 "
        "{%0,%1,%2,%3}, {%4,%5,%6,%7}, {%8,%9}, {%0,%1,%2,%3};"
        : "+f"(c[0]), "+f"(c[1]), "+f"(c[2]), "+f"(c[3])
        : "r"(a[0]), "r"(a[1]), "r"(a[2]), "r"(a[3]), "r"(b[0]), "r"(b[1]));
}
// single-pass mma from pre-rounded fp32 smem values
__device__ __forceinline__ void mma1s(float c[4], const float a[4], const float b[2]) {
    uint32_t A[4] = {__float_as_uint(a[0]), __float_as_uint(a[1]),
                     __float_as_uint(a[2]), __float_as_uint(a[3])};
    uint32_t B[2] = {__float_as_uint(b[0]), __float_as_uint(b[1])};
    mma_tf32(c, A, B);
}

// ---------------- tf32 tensor-core GEMM v2: C[M,N] (+)= A[M,K] @ B[K,N] -----
// BM=256, BN=128, BK=16, 256 threads (8 warps, 64x64 warp tiles, 4x2 grid),
// 3-stage cp.async pipeline, dynamic smem. cvt.rna on A and B in-loop
// (identical rounding points and k-order to the r8/r10 GEMM).
#define GA_STRIDE 20
#define GB_STRIDE 136
#define GEMM_AS_FLOATS (3 * 256 * GA_STRIDE)     // 15360
#define GEMM_BS_FLOATS (3 * 16 * GB_STRIDE)      // 6528
#define GEMM_SMEM_BYTES ((GEMM_AS_FLOATS + GEMM_BS_FLOATS) * 4)  // 87552

__global__ void __launch_bounds__(256) tf32gemm_k(
    const float* __restrict__ A, const float* __restrict__ B,
    float* __restrict__ C, int M, int N, int K, int acc_flag)
{
    extern __shared__ __align__(16) float gsm[];
    float* As = gsm;                     // [3][256][20]
    float* Bs = gsm + GEMM_AS_FLOATS;    // [3][16][136]

    const int tid  = threadIdx.x;
    const int bm   = blockIdx.y * 256;
    const int bn   = blockIdx.x * 128;
    const int warp = tid >> 5, lane = tid & 31;
    const int wm   = (warp >> 1) * 64;   // 0,64,128,192
    const int wn   = (warp & 1) * 64;    // 0,64
    const int g    = lane >> 2;
    const int tg   = lane & 3;

    float acc[4][8][4];
#pragma unroll
    for (int mt = 0; mt < 4; mt++)
#pragma unroll
        for (int nt = 0; nt < 8; nt++)
#pragma unroll
            for (int i = 0; i < 4; i++) acc[mt][nt][i] = 0.f;

    const int KT = K >> 4;

    auto load_stage = [&](int s, int k0) {
        float* as = As + s * 256 * GA_STRIDE;
        float* bs = Bs + s * 16 * GB_STRIDE;
#pragma unroll
        for (int i = 0; i < 4; i++) {               // A: 1024 float4/stage
            int slot = tid + i * 256;
            int m = slot >> 2, kq = (slot & 3) * 4;
            cpa16(as + m * GA_STRIDE + kq, A + (size_t)(bm + m) * K + k0 + kq);
        }
#pragma unroll
        for (int i = 0; i < 2; i++) {               // B: 512 float4/stage
            int slot = tid + i * 256;
            int bk = slot >> 5, bq = (slot & 31) * 4;
            int n = bn + bq;
            int nc = n < N - 4 ? n : N - 4;
            int bytes = (n < N) ? ((N - n) * 4 < 16 ? (N - n) * 4 : 16) : 0;
            cpa16z(bs + bk * GB_STRIDE + bq, B + (size_t)(k0 + bk) * N + nc, bytes);
        }
        cpa_commit();
    };

    load_stage(0, 0);
    if (KT > 1) load_stage(1, 16);

    for (int kt = 0; kt < KT; kt++) {
        cpa_wait1();
        __syncthreads();
        if (kt + 2 < KT) load_stage((kt + 2) % 3, (kt + 2) * 16);
        const int s = kt % 3;
        const float* as = As + s * 256 * GA_STRIDE;
        const float* bs = Bs + s * 16 * GB_STRIDE;
#pragma unroll
        for (int ks = 0; ks < 2; ks++) {
            uint32_t af[4][4];
#pragma unroll
            for (int mt = 0; mt < 4; mt++) {
                int r = wm + mt * 16 + g;
                int c = ks * 8 + tg;
                af[mt][0] = to_tf32(as[r * GA_STRIDE + c]);
                af[mt][1] = to_tf32(as[(r + 8) * GA_STRIDE + c]);
                af[mt][2] = to_tf32(as[r * GA_STRIDE + c + 4]);
                af[mt][3] = to_tf32(as[(r + 8) * GA_STRIDE + c + 4]);
            }
            uint32_t bf[8][2];
#pragma unroll
            for (int nt = 0; nt < 8; nt++) {
                int col = wn + nt * 8 + g;
                bf[nt][0] = to_tf32(bs[(ks * 8 + tg) * GB_STRIDE + col]);
                bf[nt][1] = to_tf32(bs[(ks * 8 + tg + 4) * GB_STRIDE + col]);
            }
#pragma unroll
            for (int mt = 0; mt < 4; mt++)
#pragma unroll
                for (int nt = 0; nt < 8; nt++)
                    mma_tf32(acc[mt][nt], af[mt], bf[nt]);
        }
        __syncthreads();
    }

#pragma unroll
    for (int mt = 0; mt < 4; mt++) {
        int r0 = bm + wm + mt * 16 + g;
#pragma unroll
        for (int nt = 0; nt < 8; nt++) {
            int col = bn + wn + nt * 8 + 2 * tg;
            if (col < N) {
                size_t o0 = (size_t)r0 * N + col;
                size_t o1 = (size_t)(r0 + 8) * N + col;
                if (acc_flag) {
                    C[o0]     += acc[mt][nt][0];
                    C[o0 + 1] += acc[mt][nt][1];
                    C[o1]     += acc[mt][nt][2];
                    C[o1 + 1] += acc[mt][nt][3];
                } else {
                    C[o0]     = acc[mt][nt][0];
                    C[o0 + 1] = acc[mt][nt][1];
                    C[o1]     = acc[mt][nt][2];
                    C[o1 + 1] = acc[mt][nt][3];
                }
            }
        }
    }
}

// ---------------- fp32 tiled SGEMM (tiny K=46 input GEMM) -------------------
__global__ void __launch_bounds__(128) sgemm_k(
    const float* __restrict__ A, const float* __restrict__ B,
    const float* __restrict__ bias, float* __restrict__ C,
    int M, int N, int K, int acc_flag)
{
    __shared__ __align__(16) float As[16][68];
    __shared__ __align__(16) float Bs[16][64];
    const int bm = blockIdx.y * 64;
    const int bn = blockIdx.x * 64;
    const int tid = threadIdx.x;
    const int tx = tid & 7;
    const int ty = tid >> 3;
    const int aRow = tid >> 4;
    const int aCol = tid & 15;
    const int bRow = tid >> 6;
    const int bCol = tid & 63;

    float acc[4][8];
#pragma unroll
    for (int i = 0; i < 4; i++)
#pragma unroll
        for (int j = 0; j < 8; j++) acc[i][j] = 0.f;

    for (int k0 = 0; k0 < K; k0 += 16) {
#pragma unroll
        for (int i = 0; i < 8; i++) {
            int m = bm + aRow + 8 * i;
            int k = k0 + aCol;
            As[aCol][aRow + 8 * i] = (k < K) ? A[(size_t)m * K + k] : 0.f;
        }
#pragma unroll
        for (int i = 0; i < 8; i++) {
            int k = k0 + bRow + 2 * i;
            int n = bn + bCol;
            Bs[bRow + 2 * i][bCol] = (k < K && n < N) ? B[(size_t)k * N + n] : 0.f;
        }
        __syncthreads();
#pragma unroll
        for (int k = 0; k < 16; k++) {
            float4 a4  = *(const float4*)&As[k][ty * 4];
            float4 b4a = *(const float4*)&Bs[k][tx * 8];
            float4 b4b = *(const float4*)&Bs[k][tx * 8 + 4];
            float a[4]  = {a4.x, a4.y, a4.z, a4.w};
            float bb[8] = {b4a.x, b4a.y, b4a.z, b4a.w, b4b.x, b4b.y, b4b.z, b4b.w};
#pragma unroll
            for (int i = 0; i < 4; i++)
#pragma unroll
                for (int j = 0; j < 8; j++)
                    acc[i][j] = fmaf(a[i], bb[j], acc[i][j]);
        }
        __syncthreads();
    }
#pragma unroll
    for (int i = 0; i < 4; i++) {
        int m = bm + ty * 4 + i;
#pragma unroll
        for (int j = 0; j < 8; j++) {
            int n = bn + tx * 8 + j;
            if (n < N) {
                float v = acc[i][j];
                if (bias) v += bias[n];
                size_t off = (size_t)m * N + n;
                if (acc_flag) v += C[off];
                C[off] = v;
            }
        }
    }
}

// -------- fused: depthwise conv(k=4)+bias+silu v2 (8 tok x 4 ch / thread) ---
__global__ void __launch_bounds__(256) convdt_k(
    const float* __restrict__ cw, const float* __restrict__ cb,
    const float* __restrict__ dtb, const float* __restrict__ Alog)
{
    const int CG = CONV_DIM / 4;              // 160 channel-groups
    const int convN = (BL / 8) * CG;          // 655,360 (multiple of 256)
    int idx = blockIdx.x * 256 + threadIdx.x;
    if (idx < convN) {
        int blg = idx / CG, cg = idx - blg * CG;
        int bl0 = blg * 8;                    // 8 tokens, never crosses batch
        int l0  = bl0 & (NL - 1);
        int c   = cg * 4;
        const float* base = g_zx + (size_t)bl0 * D_IN_PROJ + 512 + c;

        float4 v[11];
#pragma unroll
        for (int i = 0; i < 11; i++) {
            int off = i - 3;
            if (l0 + off >= 0)
                v[i] = *(const float4*)(base + (ptrdiff_t)off * D_IN_PROJ);
            else
                v[i] = make_float4(0.f, 0.f, 0.f, 0.f);
        }
        float4 w0 = *(const float4*)(cw + (size_t)(c + 0) * 4);
        float4 w1 = *(const float4*)(cw + (size_t)(c + 1) * 4);
        float4 w2 = *(const float4*)(cw + (size_t)(c + 2) * 4);
        float4 w3 = *(const float4*)(cw + (size_t)(c + 3) * 4);
        float4 bb = *(const float4*)(cb + c);
        const float wk0[4] = {w0.x, w0.y, w0.z, w0.w};
        const float wk1[4] = {w1.x, w1.y, w1.z, w1.w};
        const float wk2[4] = {w2.x, w2.y, w2.z, w2.w};
        const float wk3[4] = {w3.x, w3.y, w3.z, w3.w};

        float* outp = g_xc + (size_t)bl0 * CONV_DIM + c;
#pragma unroll
        for (int i = 0; i < 8; i++) {
            float a0 = bb.x, a1 = bb.y, a2 = bb.z, a3 = bb.w;
#pragma unroll
            for (int k = 0; k < 4; k++) {
                a0 = fmaf(v[i + k].x, wk0[k], a0);
                a1 = fmaf(v[i + k].y, wk1[k], a1);
                a2 = fmaf(v[i + k].z, wk2[k], a2);
                a3 = fmaf(v[i + k].w, wk3[k], a3);
            }
            float4 o;
            o.x = tf32r(a0 / (1.f + __expf(-a0)));
            o.y = tf32r(a1 / (1.f + __expf(-a1)));
            o.z = tf32r(a2 / (1.f + __expf(-a2)));
            o.w = tf32r(a3 / (1.f + __expf(-a3)));
            *(float4*)(outp + (size_t)i * CONV_DIM) = o;
        }
    } else {
        int j = idx - convN;
        if (j < BL * NHEADS) {
            int l  = j & (NL - 1);
            int bh = j >> 11;
            int b  = bh >> 3;
            int h  = bh & 7;
            float v = g_zx[((size_t)(b * NL + l)) * D_IN_PROJ + 1152 + h] + dtb[h];
            float dt = (v > 20.f) ? v : log1pf(expf(v));
            float dtA = dt * (-__expf(Alog[h]));
            ((float2*)g_sd)[j] = make_float2(dtA, dt);
        }
    }
}

// ---------------- scan v8: chunked SSD, CHUNK=64, triangle skips -------------
#define OFF_F    0                       // stage [2 buf][3 tile][64][68] (X,B,C)
#define SZ_TILE  4352                    // 64*68
#define SZ_FBUF  (3*SZ_TILE)             // 13056
#define OFF_W    (2*SZ_FBUF)             // W [64][68]
#define OFF_BW   (OFF_W + SZ_TILE)       // Bw [64][68]
#define OFF_S    (OFF_BW + SZ_TILE)      // S mirror [64][68]
#define OFF_SD   (OFF_S + SZ_TILE)       // (dtA,dt) [2 buf][64 float2]
#define OFF_SC   (OFF_SD + 256)          // s_s[64],s_dt[64],s_wq[64],s_el[64],ptot
#define SCAN_SMEM_FLOATS (OFF_SC + 260)
#define SCAN_SMEM_BYTES  (SCAN_SMEM_FLOATS * 4)

__global__ void __launch_bounds__(256) scan_k(const float* __restrict__ Dp)
{
    extern __shared__ __align__(16) float dsm[];

    const int bh = blockIdx.x;
    const int b = bh >> 3, h = bh & 7;
    const int t = threadIdx.x;
    const int w = t >> 5, lane = t & 31;
    const int g = lane >> 2, tg = lane & 3;
    const float Dh = Dp[h];

    const float* xcb = g_xc + (size_t)b * NL * CONV_DIM;
    const float* sdp = g_sd + (size_t)bh * NL * 2;

    float* s_s  = dsm + OFF_SC;
    float* s_dt = dsm + OFF_SC + 64;
    float* s_wq = dsm + OFF_SC + 128;
    float* s_el = dsm + OFF_SC + 192;

    for (int i = t; i < SZ_TILE; i += 256) dsm[OFF_S + i] = 0.f;

    float Sreg[4][4];
#pragma unroll
    for (int i = 0; i < 4; i++)
#pragma unroll
        for (int r = 0; r < 4; r++) Sreg[i][r] = 0.f;

    auto stage = [&](int buf, int l0) {
        float* fb = dsm + OFF_F + buf * SZ_FBUF;
#pragma unroll
        for (int i = 0; i < 12; i++) {
            int slot = t + i * 256;
            int tile = slot >> 10;
            int rc = slot & 1023;
            int row = rc >> 4, c4 = (rc & 15) * 4;
            const float* src = xcb + (size_t)(l0 + row) * CONV_DIM;
            const int goff = (tile == 0) ? h * HEADDIM : (tile == 1 ? 512 : 576);
            cpa16(fb + tile * SZ_TILE + row * 68 + c4, src + goff + c4);
        }
        if (t < 32)
            cpa16(dsm + OFF_SD + buf * 128 + t * 4, sdp + (size_t)l0 * 2 + t * 4);
        cpa_commit();
    };

    stage(0, 0);

    const int mb = (w & 3) * 16, c0 = (w >> 2) * 32;
    const int pm = mb, nh = c0;

    for (int ch = 0; ch < NCHUNK; ch++) {
        const int buf = ch & 1;
        const int l0 = ch * CHUNK;
        const float* fX = dsm + OFF_F + buf * SZ_FBUF;
        const float* fB = fX + SZ_TILE;
        const float* fC = fB + SZ_TILE;

        cpa_wait0();
        __syncthreads();

        if (ch + 1 < NCHUNK) stage(buf ^ 1, l0 + CHUNK);

        if (w == 0) {
            const float2* sd2 = (const float2*)(dsm + OFF_SD + buf * 128);
            float2 ua = sd2[2 * lane];
            float2 ub = sd2[2 * lane + 1];
            float ps = ua.x + ub.x;
            float sc_ = ps;
#pragma unroll
            for (int o = 1; o < 32; o <<= 1) {
                float v = __shfl_up_sync(0xffffffffu, sc_, o);
                if (lane >= o) sc_ += v;
            }
            float stot = __shfl_sync(0xffffffffu, sc_, 31);
            float s1 = sc_;
            float s0 = sc_ - ub.x;
            s_s[2 * lane]      = s0;
            s_s[2 * lane + 1]  = s1;
            s_dt[2 * lane]     = ua.y;
            s_dt[2 * lane + 1] = ub.y;
            s_wq[2 * lane]     = __expf(stot - s0) * ua.y;
            s_wq[2 * lane + 1] = __expf(stot - s1) * ub.y;
            s_el[2 * lane]     = __expf(s0);
            s_el[2 * lane + 1] = __expf(s1);
            if (lane == 31) dsm[OFF_SC + 256] = __expf(stot);
        }

        float Gacc[4][4] = {{0,0,0,0},{0,0,0,0},{0,0,0,0},{0,0,0,0}};
        if (mb + 15 >= c0) {
#pragma unroll
            for (int k8 = 0; k8 < 8; k8++) {
                int kc = k8 * 8;
                float a[4];
                a[0] = fC[(mb + g) * 68 + kc + tg];
                a[1] = fC[(mb + g + 8) * 68 + kc + tg];
                a[2] = fC[(mb + g) * 68 + kc + tg + 4];
                a[3] = fC[(mb + g + 8) * 68 + kc + tg + 4];
#pragma unroll
                for (int n8 = 0; n8 < 4; n8++) {
                    if (mb + 15 >= c0 + n8 * 8) {
                        float bv[2];
                        bv[0] = fB[(c0 + n8 * 8 + g) * 68 + kc + tg];
                        bv[1] = fB[(c0 + n8 * 8 + g) * 68 + kc + tg + 4];
                        mma1s(Gacc[n8], a, bv);
                    }
                }
            }
        }
        __syncthreads();

        {
            int la = mb + g, lb = la + 8;
#pragma unroll
            for (int n8 = 0; n8 < 4; n8++) {
                int ja = c0 + n8 * 8 + 2 * tg, jb2 = ja + 1;
                float w0_ = (la >= ja)  ? Gacc[n8][0] * __expf(s_s[la] - s_s[ja])  * s_dt[ja]  : 0.f;
                float w1_ = (la >= jb2) ? Gacc[n8][1] * __expf(s_s[la] - s_s[jb2]) * s_dt[jb2] : 0.f;
                float w2_ = (lb >= ja)  ? Gacc[n8][2] * __expf(s_s[lb] - s_s[ja])  * s_dt[ja]  : 0.f;
                float w3_ = (lb >= jb2) ? Gacc[n8][3] * __expf(s_s[lb] - s_s[jb2]) * s_dt[jb2] : 0.f;
                dsm[OFF_W + la * 68 + ja]  = tf32r(w0_);
                dsm[OFF_W + la * 68 + jb2] = tf32r(w1_);
                dsm[OFF_W + lb * 68 + ja]  = tf32r(w2_);
                dsm[OFF_W + lb * 68 + jb2] = tf32r(w3_);
            }
        }
#pragma unroll
        for (int i = 0; i < 16; i++) {
            int idx = t + i * 256;
            int r = idx >> 6, c = idx & 63;
            dsm[OFF_BW + r * 68 + c] = tf32r(s_wq[r] * fB[r * 68 + c]);
        }
        __syncthreads();

        float Y[4][4] = {{0,0,0,0},{0,0,0,0},{0,0,0,0},{0,0,0,0}};
#pragma unroll
        for (int k8 = 0; k8 < 8; k8++) {
            int kc = k8 * 8;
            if (kc > mb + 15) break;
            float a[4];
            a[0] = dsm[OFF_W + (mb + g) * 68 + kc + tg];
            a[1] = dsm[OFF_W + (mb + g + 8) * 68 + kc + tg];
            a[2] = dsm[OFF_W + (mb + g) * 68 + kc + tg + 4];
            a[3] = dsm[OFF_W + (mb + g + 8) * 68 + kc + tg + 4];
#pragma unroll
            for (int n8 = 0; n8 < 4; n8++) {
                int p = c0 + n8 * 8 + g;
                float bv[2];
                bv[0] = fX[(kc + tg) * 68 + p];
                bv[1] = fX[(kc + tg + 4) * 68 + p];
                mma1s(Y[n8], a, bv);
            }
        }
        float Y3[4][4] = {{0,0,0,0},{0,0,0,0},{0,0,0,0},{0,0,0,0}};
#pragma unroll
        for (int k8 = 0; k8 < 8; k8++) {
            int kc = k8 * 8;
            float a[4];
            a[0] = fC[(mb + g) * 68 + kc + tg];
            a[1] = fC[(mb + g + 8) * 68 + kc + tg];
            a[2] = fC[(mb + g) * 68 + kc + tg + 4];
            a[3] = fC[(mb + g + 8) * 68 + kc + tg + 4];
#pragma unroll
            for (int n8 = 0; n8 < 4; n8++) {
                int p = c0 + n8 * 8 + g;
                float bv[2];
                bv[0] = dsm[OFF_S + p * 68 + kc + tg];
                bv[1] = dsm[OFF_S + p * 68 + kc + tg + 4];
                mma1s(Y3[n8], a, bv);
            }
        }
        {
            float e0 = s_el[mb + g], e1 = s_el[mb + g + 8];
#pragma unroll
            for (int n8 = 0; n8 < 4; n8++) {
                Y[n8][0] = fmaf(e0, Y3[n8][0], Y[n8][0]);
                Y[n8][1] = fmaf(e0, Y3[n8][1], Y[n8][1]);
                Y[n8][2] = fmaf(e1, Y3[n8][2], Y[n8][2]);
                Y[n8][3] = fmaf(e1, Y3[n8][3], Y[n8][3]);
            }
        }
        {
            int la = mb + g, lb = la + 8;
            float* ya_ = g_y + ((size_t)(b * NL + l0 + la)) * D_INNER + h * HEADDIM;
            float* yb_ = g_y + ((size_t)(b * NL + l0 + lb)) * D_INNER + h * HEADDIM;
#pragma unroll
            for (int n8 = 0; n8 < 4; n8++) {
                int p0 = c0 + n8 * 8 + 2 * tg;
                ya_[p0]     = Y[n8][0] + Dh * fX[la * 68 + p0];
                ya_[p0 + 1] = Y[n8][1] + Dh * fX[la * 68 + p0 + 1];
                yb_[p0]     = Y[n8][2] + Dh * fX[lb * 68 + p0];
                yb_[p0 + 1] = Y[n8][3] + Dh * fX[lb * 68 + p0 + 1];
            }
        }
        {
            float pt = dsm[OFF_SC + 256];
#pragma unroll
            for (int n8 = 0; n8 < 4; n8++)
#pragma unroll
                for (int r = 0; r < 4; r++) Sreg[n8][r] *= pt;
#pragma unroll
            for (int k8 = 0; k8 < 8; k8++) {
                int kc = k8 * 8;
                float a[4];
                a[0] = fX[(kc + tg) * 68 + pm + g];
                a[1] = fX[(kc + tg) * 68 + pm + g + 8];
                a[2] = fX[(kc + tg + 4) * 68 + pm + g];
                a[3] = fX[(kc + tg + 4) * 68 + pm + g + 8];
#pragma unroll
                for (int n8 = 0; n8 < 4; n8++) {
                    int n = nh + n8 * 8 + g;
                    float bv[2];
                    bv[0] = dsm[OFF_BW + (kc + tg) * 68 + n];
                    bv[1] = dsm[OFF_BW + (kc + tg + 4) * 68 + n];
                    mma1s(Sreg[n8], a, bv);
                }
            }
        }
        __syncthreads();
#pragma unroll
        for (int n8 = 0; n8 < 4; n8++) {
            int n0 = nh + n8 * 8 + 2 * tg;
            dsm[OFF_S + (pm + g) * 68 + n0]         = tf32r(Sreg[n8][0]);
            dsm[OFF_S + (pm + g) * 68 + n0 + 1]     = tf32r(Sreg[n8][1]);
            dsm[OFF_S + (pm + g + 8) * 68 + n0]     = tf32r(Sreg[n8][2]);
            dsm[OFF_S + (pm + g + 8) * 68 + n0 + 1] = tf32r(Sreg[n8][3]);
        }
    }
}

// ---------------- y = rmsnorm(y * silu(z)) * rms_w (fp32 store) -------------
__global__ void __launch_bounds__(128) gate_rms_k(const float* __restrict__ rmsw)
{
    int row = blockIdx.x;
    int t = threadIdx.x;
    const float4* y4 = (const float4*)(g_y  + (size_t)row * D_INNER);
    const float4* z4 = (const float4*)(g_zx + (size_t)row * D_IN_PROJ);
    float4 yv = y4[t];
    float4 zv = z4[t];
    float4 g;
    g.x = yv.x * (zv.x / (1.f + __expf(-zv.x)));
    g.y = yv.y * (zv.y / (1.f + __expf(-zv.y)));
    g.z = yv.z * (zv.z / (1.f + __expf(-zv.z)));
    g.w = yv.w * (zv.w / (1.f + __expf(-zv.w)));
    float ss = g.x * g.x + g.y * g.y + g.z * g.z + g.w * g.w;
#pragma unroll
    for (int o = 16; o > 0; o >>= 1) ss += __shfl_xor_sync(0xffffffffu, ss, o);
    __shared__ float sb[4];
    if ((t & 31) == 0) sb[t >> 5] = ss;
    __syncthreads();
    float tot = sb[0] + sb[1] + sb[2] + sb[3];
    float sc = rsqrtf(tot * (1.f / 512.f) + 1e-5f);
    const float4* w4 = (const float4*)rmsw;
    float4 wv = w4[t];
    float4 o;
    o.x = g.x * sc * wv.x;
    o.y = g.y * sc * wv.y;
    o.z = g.z * sc * wv.z;
    o.w = g.w * sc * wv.w;
    ((float4*)(g_y + (size_t)row * D_INNER))[t] = o;
}

// ---------------- final LayerNorm (per row) + partial mean over l -----------
__global__ void __launch_bounds__(256) ln_part_k()
{
    __shared__ float sb[8];
    int b = blockIdx.x;
    int chunk = blockIdx.y;
    int c = threadIdx.x;
    int lane = c & 31, wid = c >> 5;
    float acc = 0.f;
    for (int i = 0; i < 64; i++) {
        int l = chunk * 64 + i;
        float v = g_h[((size_t)(b * NL + l)) * D_MODEL + c];
        float s = v;
#pragma unroll
        for (int o = 16; o > 0; o >>= 1) s += __shfl_xor_sync(0xffffffffu, s, o);
        if (lane == 0) sb[wid] = s;
        __syncthreads();
        float tot = sb[0] + sb[1] + sb[2] + sb[3] + sb[4] + sb[5] + sb[6] + sb[7];
        __syncthreads();
        float mu = tot * (1.f / 256.f);
        float d = v - mu;
        float s2 = d * d;
#pragma unroll
        for (int o = 16; o > 0; o >>= 1) s2 += __shfl_xor_sync(0xffffffffu, s2, o);
        if (lane == 0) sb[wid] = s2;
        __syncthreads();
        float var = (sb[0] + sb[1] + sb[2] + sb[3] + sb[4] + sb[5] + sb[6] + sb[7]) * (1.f / 256.f);
        __syncthreads();
        acc += d * rsqrtf(var + 1e-5f);
    }
    g_part[((size_t)(b * 32 + chunk)) * D_MODEL + c] = acc;
}

// ---------------- reduce partials, apply LN affine, compute heads -----------
__global__ void __launch_bounds__(256) final_k(
    const float* __restrict__ lnw, const float* __restrict__ lnb,
    const float* __restrict__ dirw, const float* __restrict__ dirb,
    const float* __restrict__ regw, const float* __restrict__ regb,
    float* __restrict__ out)
{
    __shared__ float hb[NB * D_MODEL];
    int t = threadIdx.x;
#pragma unroll
    for (int i = 0; i < (NB * D_MODEL) / 256; i++) {
        int idx = t + i * 256;
        int c = idx & 255;
        int bb = idx >> 8;
        float s = 0.f;
#pragma unroll
        for (int j = 0; j < 32; j++)
            s += g_part[((size_t)(bb * 32 + j)) * D_MODEL + c];
        hb[idx] = s * (1.f / 2048.f) * lnw[c] + lnb[c];
    }
    __syncthreads();
    if (t < NB) {
        float s = dirb[0];
        for (int c = 0; c < D_MODEL; c++) s += hb[t * D_MODEL + c] * dirw[c];
        out[t] = s;
    } else if (t < NB + NB * 3) {
        int q = t - NB;
        int bb = q / 3, j = q % 3;
        float s = regb[j];
        for (int c = 0; c < D_MODEL; c++) s += hb[bb * D_MODEL + c] * regw[c * 3 + j];
        out[NB + q] = s;
    }
}

// ---------------- launch ----------------------------------------------------
extern "C" void kernel_launch(void* const* d_in, const int* in_sizes, int n_in,
                              void* d_out, int out_size)
{
    const float* x    = (const float*)d_in[0];
    const float* inpw = (const float*)d_in[1];
    const float* inpb = (const float*)d_in[2];
    const float* ipw  = (const float*)d_in[3];
    const float* cw   = (const float*)d_in[4];
    const float* cb   = (const float*)d_in[5];
    const float* dtb  = (const float*)d_in[6];
    const float* alog = (const float*)d_in[7];
    const float* Dp   = (const float*)d_in[8];
    const float* rmsw = (const float*)d_in[9];
    const float* opw  = (const float*)d_in[10];
    const float* lnw  = (const float*)d_in[11];
    const float* lnb  = (const float*)d_in[12];
    const float* dirw = (const float*)d_in[13];
    const float* dirb = (const float*)d_in[14];
    const float* regw = (const float*)d_in[15];
    const float* regb = (const float*)d_in[16];
    float* out = (float*)d_out;

    void *ph_, *pzx_, *py_;
    cudaGetSymbolAddress(&ph_,  g_h);
    cudaGetSymbolAddress(&pzx_, g_zx);
    cudaGetSymbolAddress(&py_,  g_y);
    float* ph  = (float*)ph_;
    float* pzx = (float*)pzx_;
    float* py  = (float*)py_;

    cudaFuncSetAttribute(scan_k, cudaFuncAttributeMaxDynamicSharedMemorySize,
                         SCAN_SMEM_BYTES);
    cudaFuncSetAttribute(tf32gemm_k, cudaFuncAttributeMaxDynamicSharedMemorySize,
                         GEMM_SMEM_BYTES);

    // h = x @ inp_w + inp_b            [32768 x 256, K=46]  (fp32, tiny)
    sgemm_k<<<dim3(D_MODEL / 64, BL / 64), 128>>>(x, inpw, inpb, ph, BL, D_MODEL, NF, 0);

    const int convdt_threads = (BL / 8) * (CONV_DIM / 4) + BL * NHEADS;

    for (int i = 0; i < N_LAYERS; i++) {
        // zxbcdt = h @ in_proj_w       [32768 x 1160, K=256]  (tf32 tensor)
        tf32gemm_k<<<dim3((D_IN_PROJ + 127) / 128, BL / 256), 256, GEMM_SMEM_BYTES>>>(
            ph, ipw + (size_t)i * D_MODEL * D_IN_PROJ, pzx,
            BL, D_IN_PROJ, D_MODEL, 0);
        // conv + silu (tf32-rounded, register-shifted) + (dtA, dt) precompute
        convdt_k<<<(convdt_threads + 255) / 256, 256>>>(
            cw + (size_t)i * CONV_DIM * 4, cb + (size_t)i * CONV_DIM,
            dtb + i * NHEADS, alog + i * NHEADS);
        // chunked SSD scan (+ D*x skip), CHUNK=64, single-pass tf32
        scan_k<<<NB * NHEADS, 256, SCAN_SMEM_BYTES>>>(Dp + i * NHEADS);
        // y = rmsnorm(y * silu(z)) * rms_w
        gate_rms_k<<<BL, 128>>>(rmsw + (size_t)i * D_INNER);
        // h += y @ out_proj_w          [32768 x 256, K=512]  (tf32 tensor, accumulate)
        tf32gemm_k<<<dim3((D_MODEL + 127) / 128, BL / 256), 256, GEMM_SMEM_BYTES>>>(
            py, opw + (size_t)i * D_INNER * D_MODEL, ph,
            BL, D_MODEL, D_INNER, 1);
    }

    ln_part_k<<<dim3(NB, 32), 256>>>();
    final_k<<<1, 256>>>(lnw, lnb, dirw, dirb, regw, regb, out);
}

// round 12
// speedup vs baseline: 1.0082x; 1.0082x over previous
#include <cuda_runtime.h>
#include <cstdint>

#define NB 16
#define NL 2048
#define NF 46
#define D_MODEL 256
#define D_INNER 512
#define D_STATE 64
#define NHEADS 8
#define HEADDIM 64
#define CONV_DIM 640
#define D_IN_PROJ 1160
#define N_LAYERS 4
#define BL (NB*NL)
#define CHUNK 64
#define NCHUNK (NL/CHUNK)

// ---------------- scratch (static device globals; no runtime allocation) ----
__device__ float g_h[(size_t)BL * D_MODEL];      // residual stream
__device__ float g_zx[(size_t)BL * D_IN_PROJ];   // in_proj output
__device__ float g_xc[(size_t)BL * CONV_DIM];    // conv+silu output (tf32-rounded)
__device__ float g_sd[(size_t)BL * NHEADS * 2];  // (dtA, dt) pairs, [b*8+h][l]
__device__ float g_y[(size_t)BL * D_INNER];      // gated scan output
__device__ float g_part[NB * 32 * D_MODEL];      // LN partial sums

// ---------------- tf32 / cp.async helpers ------------------------------------
__device__ __forceinline__ uint32_t to_tf32(float x) {
    uint32_t r;
    asm("cvt.rna.tf32.f32 %0, %1;" : "=r"(r) : "f"(x));
    return r;
}
__device__ __forceinline__ float tf32r(float x) {
    return __uint_as_float(to_tf32(x));
}
__device__ __forceinline__ void cpa16(void* dst, const void* src) {
    uint32_t d = (uint32_t)__cvta_generic_to_shared(dst);
    asm volatile("cp.async.cg.shared.global [%0], [%1], 16;" :: "r"(d), "l"(src));
}
__device__ __forceinline__ void cpa16z(void* dst, const void* src, int bytes) {
    uint32_t d = (uint32_t)__cvta_generic_to_shared(dst);
    asm volatile("cp.async.cg.shared.global [%0], [%1], 16, %2;"
                 :: "r"(d), "l"(src), "r"(bytes));
}
__device__ __forceinline__ void cpa_commit() { asm volatile("cp.async.commit_group;"); }
__device__ __forceinline__ void cpa_wait0()  { asm volatile("cp.async.wait_group 0;"); }
__device__ __forceinline__ void cpa_wait1()  { asm volatile("cp.async.wait_group 1;"); }

__device__ __forceinline__ void mma_tf32(float c[4], const uint32_t a[4], const uint32_t b[2]) {
    asm volatile(
        "mma.sync.aligned.m16n8k8.row.col.f32.tf32.tf32.f32 "
        "{%0,%1,%2,%3}, {%4,%5,%6,%7}, {%8,%9}, {%0,%1,%2,%3};"
        : "+f"(c[0]), "+f"(c[1]), "+f"(c[2]), "+f"(c[3])
        : "r"(a[0]), "r"(a[1]), "r"(a[2]), "r"(a[3]), "r"(b[0]), "r"(b[1]));
}
// single-pass mma from pre-rounded fp32 smem values
__device__ __forceinline__ void mma1s(float c[4], const float a[4], const float b[2]) {
    uint32_t A[4] = {__float_as_uint(a[0]), __float_as_uint(a[1]),
                     __float_as_uint(a[2]), __float_as_uint(a[3])};
    uint32_t B[2] = {__float_as_uint(b[0]), __float_as_uint(b[1])};
    mma_tf32(c, A, B);
}

// ---------------- tf32 tensor-core GEMM (r10 config): BM=128,BN=64,BK=16 ----
__global__ void __launch_bounds__(256) tf32gemm_k(
    const float* __restrict__ A, const float* __restrict__ B,
    float* __restrict__ C, int M, int N, int K, int acc_flag)
{
    __shared__ __align__(16) float As[3][128][20];
    __shared__ __align__(16) float Bs[3][16][72];

    const int tid  = threadIdx.x;
    const int bm   = blockIdx.y * 128;
    const int bn   = blockIdx.x * 64;
    const int warp = tid >> 5, lane = tid & 31;
    const int wm   = (warp >> 1) * 32;
    const int wn   = (warp & 1) * 32;
    const int g    = lane >> 2;
    const int tg   = lane & 3;

    float acc[2][4][4];
#pragma unroll
    for (int mt = 0; mt < 2; mt++)
#pragma unroll
        for (int nt = 0; nt < 4; nt++)
#pragma unroll
            for (int i = 0; i < 4; i++) acc[mt][nt][i] = 0.f;

    const int KT = K >> 4;
    const int b_k  = tid >> 4;
    const int b_nq = (tid & 15) * 4;

    auto load_stage = [&](int s, int k0) {
#pragma unroll
        for (int i = 0; i < 2; i++) {
            int idx = tid * 2 + i;
            int m = idx >> 2, kq = (idx & 3) * 4;
            cpa16(&As[s][m][kq], A + (size_t)(bm + m) * K + k0 + kq);
        }
        {
            int n = bn + b_nq;
            int nc = n < N - 4 ? n : N - 4;
            int bytes = (n < N) ? ((N - n) * 4 < 16 ? (N - n) * 4 : 16) : 0;
            cpa16z(&Bs[s][b_k][b_nq], B + (size_t)(k0 + b_k) * N + nc, bytes);
        }
        cpa_commit();
    };

    load_stage(0, 0);
    if (KT > 1) load_stage(1, 16);

    for (int kt = 0; kt < KT; kt++) {
        cpa_wait1();
        __syncthreads();
        if (kt + 2 < KT) load_stage((kt + 2) % 3, (kt + 2) * 16);
        const int s = kt % 3;
#pragma unroll
        for (int ks = 0; ks < 2; ks++) {
            uint32_t af[2][4];
#pragma unroll
            for (int mt = 0; mt < 2; mt++) {
                int r = wm + mt * 16 + g;
                int c = ks * 8 + tg;
                af[mt][0] = to_tf32(As[s][r][c]);
                af[mt][1] = to_tf32(As[s][r + 8][c]);
                af[mt][2] = to_tf32(As[s][r][c + 4]);
                af[mt][3] = to_tf32(As[s][r + 8][c + 4]);
            }
            uint32_t bf[4][2];
#pragma unroll
            for (int nt = 0; nt < 4; nt++) {
                int col = wn + nt * 8 + g;
                bf[nt][0] = to_tf32(Bs[s][ks * 8 + tg][col]);
                bf[nt][1] = to_tf32(Bs[s][ks * 8 + tg + 4][col]);
            }
#pragma unroll
            for (int mt = 0; mt < 2; mt++)
#pragma unroll
                for (int nt = 0; nt < 4; nt++)
                    mma_tf32(acc[mt][nt], af[mt], bf[nt]);
        }
    }

#pragma unroll
    for (int mt = 0; mt < 2; mt++) {
        int r0 = bm + wm + mt * 16 + g;
#pragma unroll
        for (int nt = 0; nt < 4; nt++) {
            int col = bn + wn + nt * 8 + 2 * tg;
            if (col < N) {
                size_t o0 = (size_t)r0 * N + col;
                size_t o1 = (size_t)(r0 + 8) * N + col;
                if (acc_flag) {
                    C[o0]     += acc[mt][nt][0];
                    C[o0 + 1] += acc[mt][nt][1];
                    C[o1]     += acc[mt][nt][2];
                    C[o1 + 1] += acc[mt][nt][3];
                } else {
                    C[o0]     = acc[mt][nt][0];
                    C[o0 + 1] = acc[mt][nt][1];
                    C[o1]     = acc[mt][nt][2];
                    C[o1 + 1] = acc[mt][nt][3];
                }
            }
        }
    }
}

// ---------------- fp32 tiled SGEMM (tiny K=46 input GEMM) -------------------
__global__ void __launch_bounds__(128) sgemm_k(
    const float* __restrict__ A, const float* __restrict__ B,
    const float* __restrict__ bias, float* __restrict__ C,
    int M, int N, int K, int acc_flag)
{
    __shared__ __align__(16) float As[16][68];
    __shared__ __align__(16) float Bs[16][64];
    const int bm = blockIdx.y * 64;
    const int bn = blockIdx.x * 64;
    const int tid = threadIdx.x;
    const int tx = tid & 7;
    const int ty = tid >> 3;
    const int aRow = tid >> 4;
    const int aCol = tid & 15;
    const int bRow = tid >> 6;
    const int bCol = tid & 63;

    float acc[4][8];
#pragma unroll
    for (int i = 0; i < 4; i++)
#pragma unroll
        for (int j = 0; j < 8; j++) acc[i][j] = 0.f;

    for (int k0 = 0; k0 < K; k0 += 16) {
#pragma unroll
        for (int i = 0; i < 8; i++) {
            int m = bm + aRow + 8 * i;
            int k = k0 + aCol;
            As[aCol][aRow + 8 * i] = (k < K) ? A[(size_t)m * K + k] : 0.f;
        }
#pragma unroll
        for (int i = 0; i < 8; i++) {
            int k = k0 + bRow + 2 * i;
            int n = bn + bCol;
            Bs[bRow + 2 * i][bCol] = (k < K && n < N) ? B[(size_t)k * N + n] : 0.f;
        }
        __syncthreads();
#pragma unroll
        for (int k = 0; k < 16; k++) {
            float4 a4  = *(const float4*)&As[k][ty * 4];
            float4 b4a = *(const float4*)&Bs[k][tx * 8];
            float4 b4b = *(const float4*)&Bs[k][tx * 8 + 4];
            float a[4]  = {a4.x, a4.y, a4.z, a4.w};
            float bb[8] = {b4a.x, b4a.y, b4a.z, b4a.w, b4b.x, b4b.y, b4b.z, b4b.w};
#pragma unroll
            for (int i = 0; i < 4; i++)
#pragma unroll
                for (int j = 0; j < 8; j++)
                    acc[i][j] = fmaf(a[i], bb[j], acc[i][j]);
        }
        __syncthreads();
    }
#pragma unroll
    for (int i = 0; i < 4; i++) {
        int m = bm + ty * 4 + i;
#pragma unroll
        for (int j = 0; j < 8; j++) {
            int n = bn + tx * 8 + j;
            if (n < N) {
                float v = acc[i][j];
                if (bias) v += bias[n];
                size_t off = (size_t)m * N + n;
                if (acc_flag) v += C[off];
                C[off] = v;
            }
        }
    }
}

// -------- fused: depthwise conv(k=4)+bias+silu v2 (8 tok x 4 ch / thread) ---
__global__ void __launch_bounds__(256) convdt_k(
    const float* __restrict__ cw, const float* __restrict__ cb,
    const float* __restrict__ dtb, const float* __restrict__ Alog)
{
    const int CG = CONV_DIM / 4;              // 160 channel-groups
    const int convN = (BL / 8) * CG;          // 655,360 (multiple of 256)
    int idx = blockIdx.x * 256 + threadIdx.x;
    if (idx < convN) {
        int blg = idx / CG, cg = idx - blg * CG;
        int bl0 = blg * 8;                    // 8 tokens, never crosses batch
        int l0  = bl0 & (NL - 1);
        int c   = cg * 4;
        const float* base = g_zx + (size_t)bl0 * D_IN_PROJ + 512 + c;

        float4 v[11];
#pragma unroll
        for (int i = 0; i < 11; i++) {
            int off = i - 3;
            if (l0 + off >= 0)
                v[i] = *(const float4*)(base + (ptrdiff_t)off * D_IN_PROJ);
            else
                v[i] = make_float4(0.f, 0.f, 0.f, 0.f);
        }
        float4 w0 = *(const float4*)(cw + (size_t)(c + 0) * 4);
        float4 w1 = *(const float4*)(cw + (size_t)(c + 1) * 4);
        float4 w2 = *(const float4*)(cw + (size_t)(c + 2) * 4);
        float4 w3 = *(const float4*)(cw + (size_t)(c + 3) * 4);
        float4 bb = *(const float4*)(cb + c);
        const float wk0[4] = {w0.x, w0.y, w0.z, w0.w};
        const float wk1[4] = {w1.x, w1.y, w1.z, w1.w};
        const float wk2[4] = {w2.x, w2.y, w2.z, w2.w};
        const float wk3[4] = {w3.x, w3.y, w3.z, w3.w};

        float* outp = g_xc + (size_t)bl0 * CONV_DIM + c;
#pragma unroll
        for (int i = 0; i < 8; i++) {
            float a0 = bb.x, a1 = bb.y, a2 = bb.z, a3 = bb.w;
#pragma unroll
            for (int k = 0; k < 4; k++) {
                a0 = fmaf(v[i + k].x, wk0[k], a0);
                a1 = fmaf(v[i + k].y, wk1[k], a1);
                a2 = fmaf(v[i + k].z, wk2[k], a2);
                a3 = fmaf(v[i + k].w, wk3[k], a3);
            }
            float4 o;
            o.x = tf32r(a0 / (1.f + __expf(-a0)));
            o.y = tf32r(a1 / (1.f + __expf(-a1)));
            o.z = tf32r(a2 / (1.f + __expf(-a2)));
            o.w = tf32r(a3 / (1.f + __expf(-a3)));
            *(float4*)(outp + (size_t)i * CONV_DIM) = o;
        }
    } else {
        int j = idx - convN;
        if (j < BL * NHEADS) {
            int l  = j & (NL - 1);
            int bh = j >> 11;
            int b  = bh >> 3;
            int h  = bh & 7;
            float v = g_zx[((size_t)(b * NL + l)) * D_IN_PROJ + 1152 + h] + dtb[h];
            float dt = (v > 20.f) ? v : log1pf(expf(v));
            float dtA = dt * (-__expf(Alog[h]));
            ((float2*)g_sd)[j] = make_float2(dtA, dt);
        }
    }
}

// ---------------- scan v9: chunked SSD + fused silu(z) gate ------------------
// Stage 4 tiles per buf: X, B, C (from g_xc) and Z (from g_zx head slice).
// Epilogue writes y = (Y + D*x) * silu(z)  (same formula as old gate_rms).
#define OFF_F    0                       // stage [2 buf][4 tile][64][68]
#define SZ_TILE  4352                    // 64*68
#define SZ_FBUF  (4*SZ_TILE)             // 17408
#define OFF_W    (2*SZ_FBUF)             // W [64][68]
#define OFF_BW   (OFF_W + SZ_TILE)       // Bw [64][68]
#define OFF_S    (OFF_BW + SZ_TILE)      // S mirror [64][68]
#define OFF_SD   (OFF_S + SZ_TILE)       // (dtA,dt) [2 buf][64 float2]
#define OFF_SC   (OFF_SD + 256)          // s_s[64],s_dt[64],s_wq[64],s_el[64],ptot
#define SCAN_SMEM_FLOATS (OFF_SC + 260)
#define SCAN_SMEM_BYTES  (SCAN_SMEM_FLOATS * 4)

__global__ void __launch_bounds__(256) scan_k(const float* __restrict__ Dp)
{
    extern __shared__ __align__(16) float dsm[];

    const int bh = blockIdx.x;
    const int b = bh >> 3, h = bh & 7;
    const int t = threadIdx.x;
    const int w = t >> 5, lane = t & 31;
    const int g = lane >> 2, tg = lane & 3;
    const float Dh = Dp[h];

    const float* xcb = g_xc + (size_t)b * NL * CONV_DIM;
    const float* zcb = g_zx + (size_t)b * NL * D_IN_PROJ + h * HEADDIM;
    const float* sdp = g_sd + (size_t)bh * NL * 2;

    float* s_s  = dsm + OFF_SC;
    float* s_dt = dsm + OFF_SC + 64;
    float* s_wq = dsm + OFF_SC + 128;
    float* s_el = dsm + OFF_SC + 192;

    for (int i = t; i < SZ_TILE; i += 256) dsm[OFF_S + i] = 0.f;

    float Sreg[4][4];
#pragma unroll
    for (int i = 0; i < 4; i++)
#pragma unroll
        for (int r = 0; r < 4; r++) Sreg[i][r] = 0.f;

    // stage loader: 4096 float4 (X,B,C,Z) + 32 float4 (sd)
    auto stage = [&](int buf, int l0) {
        float* fb = dsm + OFF_F + buf * SZ_FBUF;
#pragma unroll
        for (int i = 0; i < 16; i++) {
            int slot = t + i * 256;
            int tile = slot >> 10;
            int rc = slot & 1023;
            int row = rc >> 4, c4 = (rc & 15) * 4;
            const float* src;
            if (tile < 3) {
                const int goff = (tile == 0) ? h * HEADDIM : (tile == 1 ? 512 : 576);
                src = xcb + (size_t)(l0 + row) * CONV_DIM + goff + c4;
            } else {
                src = zcb + (size_t)(l0 + row) * D_IN_PROJ + c4;
            }
            cpa16(fb + tile * SZ_TILE + row * 68 + c4, src);
        }
        if (t < 32)
            cpa16(dsm + OFF_SD + buf * 128 + t * 4, sdp + (size_t)l0 * 2 + t * 4);
        cpa_commit();
    };

    stage(0, 0);

    const int mb = (w & 3) * 16, c0 = (w >> 2) * 32;
    const int pm = mb, nh = c0;

    for (int ch = 0; ch < NCHUNK; ch++) {
        const int buf = ch & 1;
        const int l0 = ch * CHUNK;
        const float* fX = dsm + OFF_F + buf * SZ_FBUF;
        const float* fB = fX + SZ_TILE;
        const float* fC = fB + SZ_TILE;
        const float* fZ = fC + SZ_TILE;

        cpa_wait0();
        __syncthreads();

        if (ch + 1 < NCHUNK) stage(buf ^ 1, l0 + CHUNK);

        if (w == 0) {
            const float2* sd2 = (const float2*)(dsm + OFF_SD + buf * 128);
            float2 ua = sd2[2 * lane];
            float2 ub = sd2[2 * lane + 1];
            float ps = ua.x + ub.x;
            float sc_ = ps;
#pragma unroll
            for (int o = 1; o < 32; o <<= 1) {
                float v = __shfl_up_sync(0xffffffffu, sc_, o);
                if (lane >= o) sc_ += v;
            }
            float stot = __shfl_sync(0xffffffffu, sc_, 31);
            float s1 = sc_;
            float s0 = sc_ - ub.x;
            s_s[2 * lane]      = s0;
            s_s[2 * lane + 1]  = s1;
            s_dt[2 * lane]     = ua.y;
            s_dt[2 * lane + 1] = ub.y;
            s_wq[2 * lane]     = __expf(stot - s0) * ua.y;
            s_wq[2 * lane + 1] = __expf(stot - s1) * ub.y;
            s_el[2 * lane]     = __expf(s0);
            s_el[2 * lane + 1] = __expf(s1);
            if (lane == 31) dsm[OFF_SC + 256] = __expf(stot);
        }

        float Gacc[4][4] = {{0,0,0,0},{0,0,0,0},{0,0,0,0},{0,0,0,0}};
        if (mb + 15 >= c0) {
#pragma unroll
            for (int k8 = 0; k8 < 8; k8++) {
                int kc = k8 * 8;
                float a[4];
                a[0] = fC[(mb + g) * 68 + kc + tg];
                a[1] = fC[(mb + g + 8) * 68 + kc + tg];
                a[2] = fC[(mb + g) * 68 + kc + tg + 4];
                a[3] = fC[(mb + g + 8) * 68 + kc + tg + 4];
#pragma unroll
                for (int n8 = 0; n8 < 4; n8++) {
                    if (mb + 15 >= c0 + n8 * 8) {
                        float bv[2];
                        bv[0] = fB[(c0 + n8 * 8 + g) * 68 + kc + tg];
                        bv[1] = fB[(c0 + n8 * 8 + g) * 68 + kc + tg + 4];
                        mma1s(Gacc[n8], a, bv);
                    }
                }
            }
        }
        __syncthreads();

        {
            int la = mb + g, lb = la + 8;
#pragma unroll
            for (int n8 = 0; n8 < 4; n8++) {
                int ja = c0 + n8 * 8 + 2 * tg, jb2 = ja + 1;
                float w0_ = (la >= ja)  ? Gacc[n8][0] * __expf(s_s[la] - s_s[ja])  * s_dt[ja]  : 0.f;
                float w1_ = (la >= jb2) ? Gacc[n8][1] * __expf(s_s[la] - s_s[jb2]) * s_dt[jb2] : 0.f;
                float w2_ = (lb >= ja)  ? Gacc[n8][2] * __expf(s_s[lb] - s_s[ja])  * s_dt[ja]  : 0.f;
                float w3_ = (lb >= jb2) ? Gacc[n8][3] * __expf(s_s[lb] - s_s[jb2]) * s_dt[jb2] : 0.f;
                dsm[OFF_W + la * 68 + ja]  = tf32r(w0_);
                dsm[OFF_W + la * 68 + jb2] = tf32r(w1_);
                dsm[OFF_W + lb * 68 + ja]  = tf32r(w2_);
                dsm[OFF_W + lb * 68 + jb2] = tf32r(w3_);
            }
        }
#pragma unroll
        for (int i = 0; i < 16; i++) {
            int idx = t + i * 256;
            int r = idx >> 6, c = idx & 63;
            dsm[OFF_BW + r * 68 + c] = tf32r(s_wq[r] * fB[r * 68 + c]);
        }
        __syncthreads();

        float Y[4][4] = {{0,0,0,0},{0,0,0,0},{0,0,0,0},{0,0,0,0}};
#pragma unroll
        for (int k8 = 0; k8 < 8; k8++) {
            int kc = k8 * 8;
            if (kc > mb + 15) break;
            float a[4];
            a[0] = dsm[OFF_W + (mb + g) * 68 + kc + tg];
            a[1] = dsm[OFF_W + (mb + g + 8) * 68 + kc + tg];
            a[2] = dsm[OFF_W + (mb + g) * 68 + kc + tg + 4];
            a[3] = dsm[OFF_W + (mb + g + 8) * 68 + kc + tg + 4];
#pragma unroll
            for (int n8 = 0; n8 < 4; n8++) {
                int p = c0 + n8 * 8 + g;
                float bv[2];
                bv[0] = fX[(kc + tg) * 68 + p];
                bv[1] = fX[(kc + tg + 4) * 68 + p];
                mma1s(Y[n8], a, bv);
            }
        }
        float Y3[4][4] = {{0,0,0,0},{0,0,0,0},{0,0,0,0},{0,0,0,0}};
#pragma unroll
        for (int k8 = 0; k8 < 8; k8++) {
            int kc = k8 * 8;
            float a[4];
            a[0] = fC[(mb + g) * 68 + kc + tg];
            a[1] = fC[(mb + g + 8) * 68 + kc + tg];
            a[2] = fC[(mb + g) * 68 + kc + tg + 4];
            a[3] = fC[(mb + g + 8) * 68 + kc + tg + 4];
#pragma unroll
            for (int n8 = 0; n8 < 4; n8++) {
                int p = c0 + n8 * 8 + g;
                float bv[2];
                bv[0] = dsm[OFF_S + p * 68 + kc + tg];
                bv[1] = dsm[OFF_S + p * 68 + kc + tg + 4];
                mma1s(Y3[n8], a, bv);
            }
        }
        {
            float e0 = s_el[mb + g], e1 = s_el[mb + g + 8];
#pragma unroll
            for (int n8 = 0; n8 < 4; n8++) {
                Y[n8][0] = fmaf(e0, Y3[n8][0], Y[n8][0]);
                Y[n8][1] = fmaf(e0, Y3[n8][1], Y[n8][1]);
                Y[n8][2] = fmaf(e1, Y3[n8][2], Y[n8][2]);
                Y[n8][3] = fmaf(e1, Y3[n8][3], Y[n8][3]);
            }
        }
        // ---- y epilogue: y = (Y + D*x) * silu(z) ----
        {
            int la = mb + g, lb = la + 8;
            float* ya_ = g_y + ((size_t)(b * NL + l0 + la)) * D_INNER + h * HEADDIM;
            float* yb_ = g_y + ((size_t)(b * NL + l0 + lb)) * D_INNER + h * HEADDIM;
#pragma unroll
            for (int n8 = 0; n8 < 4; n8++) {
                int p0 = c0 + n8 * 8 + 2 * tg;
                float za0 = fZ[la * 68 + p0],     za1 = fZ[la * 68 + p0 + 1];
                float zb0 = fZ[lb * 68 + p0],     zb1 = fZ[lb * 68 + p0 + 1];
                float sa0 = za0 / (1.f + __expf(-za0));
                float sa1 = za1 / (1.f + __expf(-za1));
                float sb0 = zb0 / (1.f + __expf(-zb0));
                float sb1 = zb1 / (1.f + __expf(-zb1));
                ya_[p0]     = fmaf(Dh, fX[la * 68 + p0],     Y[n8][0]) * sa0;
                ya_[p0 + 1] = fmaf(Dh, fX[la * 68 + p0 + 1], Y[n8][1]) * sa1;
                yb_[p0]     = fmaf(Dh, fX[lb * 68 + p0],     Y[n8][2]) * sb0;
                yb_[p0 + 1] = fmaf(Dh, fX[lb * 68 + p0 + 1], Y[n8][3]) * sb1;
            }
        }
        {
            float pt = dsm[OFF_SC + 256];
#pragma unroll
            for (int n8 = 0; n8 < 4; n8++)
#pragma unroll
                for (int r = 0; r < 4; r++) Sreg[n8][r] *= pt;
#pragma unroll
            for (int k8 = 0; k8 < 8; k8++) {
                int kc = k8 * 8;
                float a[4];
                a[0] = fX[(kc + tg) * 68 + pm + g];
                a[1] = fX[(kc + tg) * 68 + pm + g + 8];
                a[2] = fX[(kc + tg + 4) * 68 + pm + g];
                a[3] = fX[(kc + tg + 4) * 68 + pm + g + 8];
#pragma unroll
                for (int n8 = 0; n8 < 4; n8++) {
                    int n = nh + n8 * 8 + g;
                    float bv[2];
                    bv[0] = dsm[OFF_BW + (kc + tg) * 68 + n];
                    bv[1] = dsm[OFF_BW + (kc + tg + 4) * 68 + n];
                    mma1s(Sreg[n8], a, bv);
                }
            }
        }
        __syncthreads();
#pragma unroll
        for (int n8 = 0; n8 < 4; n8++) {
            int n0 = nh + n8 * 8 + 2 * tg;
            dsm[OFF_S + (pm + g) * 68 + n0]         = tf32r(Sreg[n8][0]);
            dsm[OFF_S + (pm + g) * 68 + n0 + 1]     = tf32r(Sreg[n8][1]);
            dsm[OFF_S + (pm + g + 8) * 68 + n0]     = tf32r(Sreg[n8][2]);
            dsm[OFF_S + (pm + g + 8) * 68 + n0 + 1] = tf32r(Sreg[n8][3]);
        }
    }
}

// ---------------- rms: y = y * rsqrt(mean(y^2)+eps) * rms_w -----------------
// Warp-per-row: 256 threads = 8 warps = 8 rows/block; pure shfl reduction.
__global__ void __launch_bounds__(256) rms_k(const float* __restrict__ rmsw)
{
    int w = threadIdx.x >> 5, lane = threadIdx.x & 31;
    size_t row = (size_t)blockIdx.x * 8 + w;
    float4* y4 = (float4*)(g_y + row * D_INNER);
    float4 v[4];
    float ss = 0.f;
#pragma unroll
    for (int i = 0; i < 4; i++) {
        v[i] = y4[lane + i * 32];
        ss += v[i].x * v[i].x + v[i].y * v[i].y + v[i].z * v[i].z + v[i].w * v[i].w;
    }
#pragma unroll
    for (int o = 16; o > 0; o >>= 1) ss += __shfl_xor_sync(0xffffffffu, ss, o);
    float sc = rsqrtf(ss * (1.f / 512.f) + 1e-5f);
#pragma unroll
    for (int i = 0; i < 4; i++) {
        float4 wv = ((const float4*)rmsw)[lane + i * 32];
        float4 o;
        o.x = v[i].x * sc * wv.x;
        o.y = v[i].y * sc * wv.y;
        o.z = v[i].z * sc * wv.z;
        o.w = v[i].w * sc * wv.w;
        y4[lane + i * 32] = o;
    }
}

// ---------------- final LayerNorm (per row) + partial mean over l -----------
__global__ void __launch_bounds__(256) ln_part_k()
{
    __shared__ float sb[8];
    int b = blockIdx.x;
    int chunk = blockIdx.y;
    int c = threadIdx.x;
    int lane = c & 31, wid = c >> 5;
    float acc = 0.f;
    for (int i = 0; i < 64; i++) {
        int l = chunk * 64 + i;
        float v = g_h[((size_t)(b * NL + l)) * D_MODEL + c];
        float s = v;
#pragma unroll
        for (int o = 16; o > 0; o >>= 1) s += __shfl_xor_sync(0xffffffffu, s, o);
        if (lane == 0) sb[wid] = s;
        __syncthreads();
        float tot = sb[0] + sb[1] + sb[2] + sb[3] + sb[4] + sb[5] + sb[6] + sb[7];
        __syncthreads();
        float mu = tot * (1.f / 256.f);
        float d = v - mu;
        float s2 = d * d;
#pragma unroll
        for (int o = 16; o > 0; o >>= 1) s2 += __shfl_xor_sync(0xffffffffu, s2, o);
        if (lane == 0) sb[wid] = s2;
        __syncthreads();
        float var = (sb[0] + sb[1] + sb[2] + sb[3] + sb[4] + sb[5] + sb[6] + sb[7]) * (1.f / 256.f);
        __syncthreads();
        acc += d * rsqrtf(var + 1e-5f);
    }
    g_part[((size_t)(b * 32 + chunk)) * D_MODEL + c] = acc;
}

// ---------------- reduce partials, apply LN affine, compute heads -----------
__global__ void __launch_bounds__(256) final_k(
    const float* __restrict__ lnw, const float* __restrict__ lnb,
    const float* __restrict__ dirw, const float* __restrict__ dirb,
    const float* __restrict__ regw, const float* __restrict__ regb,
    float* __restrict__ out)
{
    __shared__ float hb[NB * D_MODEL];
    int t = threadIdx.x;
#pragma unroll
    for (int i = 0; i < (NB * D_MODEL) / 256; i++) {
        int idx = t + i * 256;
        int c = idx & 255;
        int bb = idx >> 8;
        float s = 0.f;
#pragma unroll
        for (int j = 0; j < 32; j++)
            s += g_part[((size_t)(bb * 32 + j)) * D_MODEL + c];
        hb[idx] = s * (1.f / 2048.f) * lnw[c] + lnb[c];
    }
    __syncthreads();
    if (t < NB) {
        float s = dirb[0];
        for (int c = 0; c < D_MODEL; c++) s += hb[t * D_MODEL + c] * dirw[c];
        out[t] = s;
    } else if (t < NB + NB * 3) {
        int q = t - NB;
        int bb = q / 3, j = q % 3;
        float s = regb[j];
        for (int c = 0; c < D_MODEL; c++) s += hb[bb * D_MODEL + c] * regw[c * 3 + j];
        out[NB + q] = s;
    }
}

// ---------------- launch ----------------------------------------------------
extern "C" void kernel_launch(void* const* d_in, const int* in_sizes, int n_in,
                              void* d_out, int out_size)
{
    const float* x    = (const float*)d_in[0];
    const float* inpw = (const float*)d_in[1];
    const float* inpb = (const float*)d_in[2];
    const float* ipw  = (const float*)d_in[3];
    const float* cw   = (const float*)d_in[4];
    const float* cb   = (const float*)d_in[5];
    const float* dtb  = (const float*)d_in[6];
    const float* alog = (const float*)d_in[7];
    const float* Dp   = (const float*)d_in[8];
    const float* rmsw = (const float*)d_in[9];
    const float* opw  = (const float*)d_in[10];
    const float* lnw  = (const float*)d_in[11];
    const float* lnb  = (const float*)d_in[12];
    const float* dirw = (const float*)d_in[13];
    const float* dirb = (const float*)d_in[14];
    const float* regw = (const float*)d_in[15];
    const float* regb = (const float*)d_in[16];
    float* out = (float*)d_out;

    void *ph_, *pzx_, *py_;
    cudaGetSymbolAddress(&ph_,  g_h);
    cudaGetSymbolAddress(&pzx_, g_zx);
    cudaGetSymbolAddress(&py_,  g_y);
    float* ph  = (float*)ph_;
    float* pzx = (float*)pzx_;
    float* py  = (float*)py_;

    cudaFuncSetAttribute(scan_k, cudaFuncAttributeMaxDynamicSharedMemorySize,
                         SCAN_SMEM_BYTES);

    // h = x @ inp_w + inp_b            [32768 x 256, K=46]  (fp32, tiny)
    sgemm_k<<<dim3(D_MODEL / 64, BL / 64), 128>>>(x, inpw, inpb, ph, BL, D_MODEL, NF, 0);

    const int convdt_threads = (BL / 8) * (CONV_DIM / 4) + BL * NHEADS;

    for (int i = 0; i < N_LAYERS; i++) {
        // zxbcdt = h @ in_proj_w       [32768 x 1160, K=256]  (tf32 tensor)
        tf32gemm_k<<<dim3((D_IN_PROJ + 63) / 64, BL / 128), 256>>>(
            ph, ipw + (size_t)i * D_MODEL * D_IN_PROJ, pzx,
            BL, D_IN_PROJ, D_MODEL, 0);
        // conv + silu (tf32-rounded, register-shifted) + (dtA, dt) precompute
        convdt_k<<<(convdt_threads + 255) / 256, 256>>>(
            cw + (size_t)i * CONV_DIM * 4, cb + (size_t)i * CONV_DIM,
            dtb + i * NHEADS, alog + i * NHEADS);
        // chunked SSD scan + D*x skip + fused silu(z) gate
        scan_k<<<NB * NHEADS, 256, SCAN_SMEM_BYTES>>>(Dp + i * NHEADS);
        // y = rmsnorm(y) * rms_w  (warp-per-row)
        rms_k<<<BL / 8, 256>>>(rmsw + (size_t)i * D_INNER);
        // h += y @ out_proj_w          [32768 x 256, K=512]  (tf32 tensor, accumulate)
        tf32gemm_k<<<dim3(D_MODEL / 64, BL / 128), 256>>>(
            py, opw + (size_t)i * D_INNER * D_MODEL, ph,
            BL, D_MODEL, D_INNER, 1);
    }

    ln_part_k<<<dim3(NB, 32), 256>>>();
    final_k<<<1, 256>>>(lnw, lnb, dirw, dirb, regw, regb, out);
}

// round 13
// speedup vs baseline: 1.0262x; 1.0178x over previous
#include <cuda_runtime.h>
#include <cstdint>

#define NB 16
#define NL 2048
#define NF 46
#define D_MODEL 256
#define D_INNER 512
#define D_STATE 64
#define NHEADS 8
#define HEADDIM 64
#define CONV_DIM 640
#define D_IN_PROJ 1160
#define N_LAYERS 4
#define BL (NB*NL)
#define CHUNK 64
#define NCHUNK (NL/CHUNK)

// ---------------- scratch (static device globals; no runtime allocation) ----
__device__ float g_h[(size_t)BL * D_MODEL];      // residual stream
__device__ float g_zx[(size_t)BL * D_IN_PROJ];   // in_proj output
__device__ float g_xc[(size_t)BL * CONV_DIM];    // conv+silu output (tf32-rounded)
__device__ float g_sd[(size_t)BL * NHEADS * 2];  // (dtA, dt) pairs, [b*8+h][l]
__device__ float g_y[(size_t)BL * D_INNER];      // scan output / gated-norm
__device__ float g_part[NB * 32 * D_MODEL];      // LN partial sums

// ---------------- tf32 / cp.async helpers ------------------------------------
__device__ __forceinline__ uint32_t to_tf32(float x) {
    uint32_t r;
    asm("cvt.rna.tf32.f32 %0, %1;" : "=r"(r) : "f"(x));
    return r;
}
__device__ __forceinline__ float tf32r(float x) {
    return __uint_as_float(to_tf32(x));
}
__device__ __forceinline__ void cpa16(void* dst, const void* src) {
    uint32_t d = (uint32_t)__cvta_generic_to_shared(dst);
    asm volatile("cp.async.cg.shared.global [%0], [%1], 16;" :: "r"(d), "l"(src));
}
__device__ __forceinline__ void cpa16z(void* dst, const void* src, int bytes) {
    uint32_t d = (uint32_t)__cvta_generic_to_shared(dst);
    asm volatile("cp.async.cg.shared.global [%0], [%1], 16, %2;"
                 :: "r"(d), "l"(src), "r"(bytes));
}
__device__ __forceinline__ void cpa_commit() { asm volatile("cp.async.commit_group;"); }
__device__ __forceinline__ void cpa_wait0()  { asm volatile("cp.async.wait_group 0;"); }
__device__ __forceinline__ void cpa_wait1()  { asm volatile("cp.async.wait_group 1;"); }

__device__ __forceinline__ void mma_tf32(float c[4], const uint32_t a[4], const uint32_t b[2]) {
    asm volatile(
        "mma.sync.aligned.m16n8k8.row.col.f32.tf32.tf32.f32 "
        "{%0,%1,%2,%3}, {%4,%5,%6,%7}, {%8,%9}, {%0,%1,%2,%3};"
        : "+f"(c[0]), "+f"(c[1]), "+f"(c[2]), "+f"(c[3])
        : "r"(a[0]), "r"(a[1]), "r"(a[2]), "r"(a[3]), "r"(b[0]), "r"(b[1]));
}
// single-pass mma from pre-rounded fp32 smem values
__device__ __forceinline__ void mma1s(float c[4], const float a[4], const float b[2]) {
    uint32_t A[4] = {__float_as_uint(a[0]), __float_as_uint(a[1]),
                     __float_as_uint(a[2]), __float_as_uint(a[3])};
    uint32_t B[2] = {__float_as_uint(b[0]), __float_as_uint(b[1])};
    mma_tf32(c, A, B);
}

// ---------------- tf32 tensor-core GEMM (r10 config): BM=128,BN=64,BK=16 ----
__global__ void __launch_bounds__(256) tf32gemm_k(
    const float* __restrict__ A, const float* __restrict__ B,
    float* __restrict__ C, int M, int N, int K, int acc_flag)
{
    __shared__ __align__(16) float As[3][128][20];
    __shared__ __align__(16) float Bs[3][16][72];

    const int tid  = threadIdx.x;
    const int bm   = blockIdx.y * 128;
    const int bn   = blockIdx.x * 64;
    const int warp = tid >> 5, lane = tid & 31;
    const int wm   = (warp >> 1) * 32;
    const int wn   = (warp & 1) * 32;
    const int g    = lane >> 2;
    const int tg   = lane & 3;

    float acc[2][4][4];
#pragma unroll
    for (int mt = 0; mt < 2; mt++)
#pragma unroll
        for (int nt = 0; nt < 4; nt++)
#pragma unroll
            for (int i = 0; i < 4; i++) acc[mt][nt][i] = 0.f;

    const int KT = K >> 4;
    const int b_k  = tid >> 4;
    const int b_nq = (tid & 15) * 4;

    auto load_stage = [&](int s, int k0) {
#pragma unroll
        for (int i = 0; i < 2; i++) {
            int idx = tid * 2 + i;
            int m = idx >> 2, kq = (idx & 3) * 4;
            cpa16(&As[s][m][kq], A + (size_t)(bm + m) * K + k0 + kq);
        }
        {
            int n = bn + b_nq;
            int nc = n < N - 4 ? n : N - 4;
            int bytes = (n < N) ? ((N - n) * 4 < 16 ? (N - n) * 4 : 16) : 0;
            cpa16z(&Bs[s][b_k][b_nq], B + (size_t)(k0 + b_k) * N + nc, bytes);
        }
        cpa_commit();
    };

    load_stage(0, 0);
    if (KT > 1) load_stage(1, 16);

    for (int kt = 0; kt < KT; kt++) {
        cpa_wait1();
        __syncthreads();
        if (kt + 2 < KT) load_stage((kt + 2) % 3, (kt + 2) * 16);
        const int s = kt % 3;
#pragma unroll
        for (int ks = 0; ks < 2; ks++) {
            uint32_t af[2][4];
#pragma unroll
            for (int mt = 0; mt < 2; mt++) {
                int r = wm + mt * 16 + g;
                int c = ks * 8 + tg;
                af[mt][0] = to_tf32(As[s][r][c]);
                af[mt][1] = to_tf32(As[s][r + 8][c]);
                af[mt][2] = to_tf32(As[s][r][c + 4]);
                af[mt][3] = to_tf32(As[s][r + 8][c + 4]);
            }
            uint32_t bf[4][2];
#pragma unroll
            for (int nt = 0; nt < 4; nt++) {
                int col = wn + nt * 8 + g;
                bf[nt][0] = to_tf32(Bs[s][ks * 8 + tg][col]);
                bf[nt][1] = to_tf32(Bs[s][ks * 8 + tg + 4][col]);
            }
#pragma unroll
            for (int mt = 0; mt < 2; mt++)
#pragma unroll
                for (int nt = 0; nt < 4; nt++)
                    mma_tf32(acc[mt][nt], af[mt], bf[nt]);
        }
    }

#pragma unroll
    for (int mt = 0; mt < 2; mt++) {
        int r0 = bm + wm + mt * 16 + g;
#pragma unroll
        for (int nt = 0; nt < 4; nt++) {
            int col = bn + wn + nt * 8 + 2 * tg;
            if (col < N) {
                size_t o0 = (size_t)r0 * N + col;
                size_t o1 = (size_t)(r0 + 8) * N + col;
                if (acc_flag) {
                    C[o0]     += acc[mt][nt][0];
                    C[o0 + 1] += acc[mt][nt][1];
                    C[o1]     += acc[mt][nt][2];
                    C[o1 + 1] += acc[mt][nt][3];
                } else {
                    C[o0]     = acc[mt][nt][0];
                    C[o0 + 1] = acc[mt][nt][1];
                    C[o1]     = acc[mt][nt][2];
                    C[o1 + 1] = acc[mt][nt][3];
                }
            }
        }
    }
}

// ---------------- fp32 tiled SGEMM (tiny K=46 input GEMM) -------------------
__global__ void __launch_bounds__(128) sgemm_k(
    const float* __restrict__ A, const float* __restrict__ B,
    const float* __restrict__ bias, float* __restrict__ C,
    int M, int N, int K, int acc_flag)
{
    __shared__ __align__(16) float As[16][68];
    __shared__ __align__(16) float Bs[16][64];
    const int bm = blockIdx.y * 64;
    const int bn = blockIdx.x * 64;
    const int tid = threadIdx.x;
    const int tx = tid & 7;
    const int ty = tid >> 3;
    const int aRow = tid >> 4;
    const int aCol = tid & 15;
    const int bRow = tid >> 6;
    const int bCol = tid & 63;

    float acc[4][8];
#pragma unroll
    for (int i = 0; i < 4; i++)
#pragma unroll
        for (int j = 0; j < 8; j++) acc[i][j] = 0.f;

    for (int k0 = 0; k0 < K; k0 += 16) {
#pragma unroll
        for (int i = 0; i < 8; i++) {
            int m = bm + aRow + 8 * i;
            int k = k0 + aCol;
            As[aCol][aRow + 8 * i] = (k < K) ? A[(size_t)m * K + k] : 0.f;
        }
#pragma unroll
        for (int i = 0; i < 8; i++) {
            int k = k0 + bRow + 2 * i;
            int n = bn + bCol;
            Bs[bRow + 2 * i][bCol] = (k < K && n < N) ? B[(size_t)k * N + n] : 0.f;
        }
        __syncthreads();
#pragma unroll
        for (int k = 0; k < 16; k++) {
            float4 a4  = *(const float4*)&As[k][ty * 4];
            float4 b4a = *(const float4*)&Bs[k][tx * 8];
            float4 b4b = *(const float4*)&Bs[k][tx * 8 + 4];
            float a[4]  = {a4.x, a4.y, a4.z, a4.w};
            float bb[8] = {b4a.x, b4a.y, b4a.z, b4a.w, b4b.x, b4b.y, b4b.z, b4b.w};
#pragma unroll
            for (int i = 0; i < 4; i++)
#pragma unroll
                for (int j = 0; j < 8; j++)
                    acc[i][j] = fmaf(a[i], bb[j], acc[i][j]);
        }
        __syncthreads();
    }
#pragma unroll
    for (int i = 0; i < 4; i++) {
        int m = bm + ty * 4 + i;
#pragma unroll
        for (int j = 0; j < 8; j++) {
            int n = bn + tx * 8 + j;
            if (n < N) {
                float v = acc[i][j];
                if (bias) v += bias[n];
                size_t off = (size_t)m * N + n;
                if (acc_flag) v += C[off];
                C[off] = v;
            }
        }
    }
}

// -------- fused: depthwise conv(k=4)+bias+silu v2 (8 tok x 4 ch / thread) ---
__global__ void __launch_bounds__(256) convdt_k(
    const float* __restrict__ cw, const float* __restrict__ cb,
    const float* __restrict__ dtb, const float* __restrict__ Alog)
{
    const int CG = CONV_DIM / 4;              // 160 channel-groups
    const int convN = (BL / 8) * CG;          // 655,360 (multiple of 256)
    int idx = blockIdx.x * 256 + threadIdx.x;
    if (idx < convN) {
        int blg = idx / CG, cg = idx - blg * CG;
        int bl0 = blg * 8;                    // 8 tokens, never crosses batch
        int l0  = bl0 & (NL - 1);
        int c   = cg * 4;
        const float* base = g_zx + (size_t)bl0 * D_IN_PROJ + 512 + c;

        float4 v[11];
#pragma unroll
        for (int i = 0; i < 11; i++) {
            int off = i - 3;
            if (l0 + off >= 0)
                v[i] = *(const float4*)(base + (ptrdiff_t)off * D_IN_PROJ);
            else
                v[i] = make_float4(0.f, 0.f, 0.f, 0.f);
        }
        float4 w0 = *(const float4*)(cw + (size_t)(c + 0) * 4);
        float4 w1 = *(const float4*)(cw + (size_t)(c + 1) * 4);
        float4 w2 = *(const float4*)(cw + (size_t)(c + 2) * 4);
        float4 w3 = *(const float4*)(cw + (size_t)(c + 3) * 4);
        float4 bb = *(const float4*)(cb + c);
        const float wk0[4] = {w0.x, w0.y, w0.z, w0.w};
        const float wk1[4] = {w1.x, w1.y, w1.z, w1.w};
        const float wk2[4] = {w2.x, w2.y, w2.z, w2.w};
        const float wk3[4] = {w3.x, w3.y, w3.z, w3.w};

        float* outp = g_xc + (size_t)bl0 * CONV_DIM + c;
#pragma unroll
        for (int i = 0; i < 8; i++) {
            float a0 = bb.x, a1 = bb.y, a2 = bb.z, a3 = bb.w;
#pragma unroll
            for (int k = 0; k < 4; k++) {
                a0 = fmaf(v[i + k].x, wk0[k], a0);
                a1 = fmaf(v[i + k].y, wk1[k], a1);
                a2 = fmaf(v[i + k].z, wk2[k], a2);
                a3 = fmaf(v[i + k].w, wk3[k], a3);
            }
            float4 o;
            o.x = tf32r(a0 / (1.f + __expf(-a0)));
            o.y = tf32r(a1 / (1.f + __expf(-a1)));
            o.z = tf32r(a2 / (1.f + __expf(-a2)));
            o.w = tf32r(a3 / (1.f + __expf(-a3)));
            *(float4*)(outp + (size_t)i * CONV_DIM) = o;
        }
    } else {
        int j = idx - convN;
        if (j < BL * NHEADS) {
            int l  = j & (NL - 1);
            int bh = j >> 11;
            int b  = bh >> 3;
            int h  = bh & 7;
            float v = g_zx[((size_t)(b * NL + l)) * D_IN_PROJ + 1152 + h] + dtb[h];
            float dt = (v > 20.f) ? v : log1pf(expf(v));
            float dtA = dt * (-__expf(Alog[h]));
            ((float2*)g_sd)[j] = make_float2(dtA, dt);
        }
    }
}

// ---------------- scan v8: chunked SSD, CHUNK=64, triangle skips -------------
#define OFF_F    0                       // stage [2 buf][3 tile][64][68] (X,B,C)
#define SZ_TILE  4352                    // 64*68
#define SZ_FBUF  (3*SZ_TILE)             // 13056
#define OFF_W    (2*SZ_FBUF)             // W [64][68]
#define OFF_BW   (OFF_W + SZ_TILE)       // Bw [64][68]
#define OFF_S    (OFF_BW + SZ_TILE)      // S mirror [64][68]
#define OFF_SD   (OFF_S + SZ_TILE)       // (dtA,dt) [2 buf][64 float2]
#define OFF_SC   (OFF_SD + 256)          // s_s[64],s_dt[64],s_wq[64],s_el[64],ptot
#define SCAN_SMEM_FLOATS (OFF_SC + 260)
#define SCAN_SMEM_BYTES  (SCAN_SMEM_FLOATS * 4)

__global__ void __launch_bounds__(256) scan_k(const float* __restrict__ Dp)
{
    extern __shared__ __align__(16) float dsm[];

    const int bh = blockIdx.x;
    const int b = bh >> 3, h = bh & 7;
    const int t = threadIdx.x;
    const int w = t >> 5, lane = t & 31;
    const int g = lane >> 2, tg = lane & 3;
    const float Dh = Dp[h];

    const float* xcb = g_xc + (size_t)b * NL * CONV_DIM;
    const float* sdp = g_sd + (size_t)bh * NL * 2;

    float* s_s  = dsm + OFF_SC;
    float* s_dt = dsm + OFF_SC + 64;
    float* s_wq = dsm + OFF_SC + 128;
    float* s_el = dsm + OFF_SC + 192;

    for (int i = t; i < SZ_TILE; i += 256) dsm[OFF_S + i] = 0.f;

    float Sreg[4][4];
#pragma unroll
    for (int i = 0; i < 4; i++)
#pragma unroll
        for (int r = 0; r < 4; r++) Sreg[i][r] = 0.f;

    auto stage = [&](int buf, int l0) {
        float* fb = dsm + OFF_F + buf * SZ_FBUF;
#pragma unroll
        for (int i = 0; i < 12; i++) {
            int slot = t + i * 256;
            int tile = slot >> 10;
            int rc = slot & 1023;
            int row = rc >> 4, c4 = (rc & 15) * 4;
            const float* src = xcb + (size_t)(l0 + row) * CONV_DIM;
            const int goff = (tile == 0) ? h * HEADDIM : (tile == 1 ? 512 : 576);
            cpa16(fb + tile * SZ_TILE + row * 68 + c4, src + goff + c4);
        }
        if (t < 32)
            cpa16(dsm + OFF_SD + buf * 128 + t * 4, sdp + (size_t)l0 * 2 + t * 4);
        cpa_commit();
    };

    stage(0, 0);

    const int mb = (w & 3) * 16, c0 = (w >> 2) * 32;
    const int pm = mb, nh = c0;

    for (int ch = 0; ch < NCHUNK; ch++) {
        const int buf = ch & 1;
        const int l0 = ch * CHUNK;
        const float* fX = dsm + OFF_F + buf * SZ_FBUF;
        const float* fB = fX + SZ_TILE;
        const float* fC = fB + SZ_TILE;

        cpa_wait0();
        __syncthreads();

        if (ch + 1 < NCHUNK) stage(buf ^ 1, l0 + CHUNK);

        if (w == 0) {
            const float2* sd2 = (const float2*)(dsm + OFF_SD + buf * 128);
            float2 ua = sd2[2 * lane];
            float2 ub = sd2[2 * lane + 1];
            float ps = ua.x + ub.x;
            float sc_ = ps;
#pragma unroll
            for (int o = 1; o < 32; o <<= 1) {
                float v = __shfl_up_sync(0xffffffffu, sc_, o);
                if (lane >= o) sc_ += v;
            }
            float stot = __shfl_sync(0xffffffffu, sc_, 31);
            float s1 = sc_;
            float s0 = sc_ - ub.x;
            s_s[2 * lane]      = s0;
            s_s[2 * lane + 1]  = s1;
            s_dt[2 * lane]     = ua.y;
            s_dt[2 * lane + 1] = ub.y;
            s_wq[2 * lane]     = __expf(stot - s0) * ua.y;
            s_wq[2 * lane + 1] = __expf(stot - s1) * ub.y;
            s_el[2 * lane]     = __expf(s0);
            s_el[2 * lane + 1] = __expf(s1);
            if (lane == 31) dsm[OFF_SC + 256] = __expf(stot);
        }

        float Gacc[4][4] = {{0,0,0,0},{0,0,0,0},{0,0,0,0},{0,0,0,0}};
        if (mb + 15 >= c0) {
#pragma unroll
            for (int k8 = 0; k8 < 8; k8++) {
                int kc = k8 * 8;
                float a[4];
                a[0] = fC[(mb + g) * 68 + kc + tg];
                a[1] = fC[(mb + g + 8) * 68 + kc + tg];
                a[2] = fC[(mb + g) * 68 + kc + tg + 4];
                a[3] = fC[(mb + g + 8) * 68 + kc + tg + 4];
#pragma unroll
                for (int n8 = 0; n8 < 4; n8++) {
                    if (mb + 15 >= c0 + n8 * 8) {
                        float bv[2];
                        bv[0] = fB[(c0 + n8 * 8 + g) * 68 + kc + tg];
                        bv[1] = fB[(c0 + n8 * 8 + g) * 68 + kc + tg + 4];
                        mma1s(Gacc[n8], a, bv);
                    }
                }
            }
        }
        __syncthreads();

        {
            int la = mb + g, lb = la + 8;
#pragma unroll
            for (int n8 = 0; n8 < 4; n8++) {
                int ja = c0 + n8 * 8 + 2 * tg, jb2 = ja + 1;
                float w0_ = (la >= ja)  ? Gacc[n8][0] * __expf(s_s[la] - s_s[ja])  * s_dt[ja]  : 0.f;
                float w1_ = (la >= jb2) ? Gacc[n8][1] * __expf(s_s[la] - s_s[jb2]) * s_dt[jb2] : 0.f;
                float w2_ = (lb >= ja)  ? Gacc[n8][2] * __expf(s_s[lb] - s_s[ja])  * s_dt[ja]  : 0.f;
                float w3_ = (lb >= jb2) ? Gacc[n8][3] * __expf(s_s[lb] - s_s[jb2]) * s_dt[jb2] : 0.f;
                dsm[OFF_W + la * 68 + ja]  = tf32r(w0_);
                dsm[OFF_W + la * 68 + jb2] = tf32r(w1_);
                dsm[OFF_W + lb * 68 + ja]  = tf32r(w2_);
                dsm[OFF_W + lb * 68 + jb2] = tf32r(w3_);
            }
        }
#pragma unroll
        for (int i = 0; i < 16; i++) {
            int idx = t + i * 256;
            int r = idx >> 6, c = idx & 63;
            dsm[OFF_BW + r * 68 + c] = tf32r(s_wq[r] * fB[r * 68 + c]);
        }
        __syncthreads();

        float Y[4][4] = {{0,0,0,0},{0,0,0,0},{0,0,0,0},{0,0,0,0}};
#pragma unroll
        for (int k8 = 0; k8 < 8; k8++) {
            int kc = k8 * 8;
            if (kc > mb + 15) break;
            float a[4];
            a[0] = dsm[OFF_W + (mb + g) * 68 + kc + tg];
            a[1] = dsm[OFF_W + (mb + g + 8) * 68 + kc + tg];
            a[2] = dsm[OFF_W + (mb + g) * 68 + kc + tg + 4];
            a[3] = dsm[OFF_W + (mb + g + 8) * 68 + kc + tg + 4];
#pragma unroll
            for (int n8 = 0; n8 < 4; n8++) {
                int p = c0 + n8 * 8 + g;
                float bv[2];
                bv[0] = fX[(kc + tg) * 68 + p];
                bv[1] = fX[(kc + tg + 4) * 68 + p];
                mma1s(Y[n8], a, bv);
            }
        }
        float Y3[4][4] = {{0,0,0,0},{0,0,0,0},{0,0,0,0},{0,0,0,0}};
#pragma unroll
        for (int k8 = 0; k8 < 8; k8++) {
            int kc = k8 * 8;
            float a[4];
            a[0] = fC[(mb + g) * 68 + kc + tg];
            a[1] = fC[(mb + g + 8) * 68 + kc + tg];
            a[2] = fC[(mb + g) * 68 + kc + tg + 4];
            a[3] = fC[(mb + g + 8) * 68 + kc + tg + 4];
#pragma unroll
            for (int n8 = 0; n8 < 4; n8++) {
                int p = c0 + n8 * 8 + g;
                float bv[2];
                bv[0] = dsm[OFF_S + p * 68 + kc + tg];
                bv[1] = dsm[OFF_S + p * 68 + kc + tg + 4];
                mma1s(Y3[n8], a, bv);
            }
        }
        {
            float e0 = s_el[mb + g], e1 = s_el[mb + g + 8];
#pragma unroll
            for (int n8 = 0; n8 < 4; n8++) {
                Y[n8][0] = fmaf(e0, Y3[n8][0], Y[n8][0]);
                Y[n8][1] = fmaf(e0, Y3[n8][1], Y[n8][1]);
                Y[n8][2] = fmaf(e1, Y3[n8][2], Y[n8][2]);
                Y[n8][3] = fmaf(e1, Y3[n8][3], Y[n8][3]);
            }
        }
        {
            int la = mb + g, lb = la + 8;
            float* ya_ = g_y + ((size_t)(b * NL + l0 + la)) * D_INNER + h * HEADDIM;
            float* yb_ = g_y + ((size_t)(b * NL + l0 + lb)) * D_INNER + h * HEADDIM;
#pragma unroll
            for (int n8 = 0; n8 < 4; n8++) {
                int p0 = c0 + n8 * 8 + 2 * tg;
                ya_[p0]     = Y[n8][0] + Dh * fX[la * 68 + p0];
                ya_[p0 + 1] = Y[n8][1] + Dh * fX[la * 68 + p0 + 1];
                yb_[p0]     = Y[n8][2] + Dh * fX[lb * 68 + p0];
                yb_[p0 + 1] = Y[n8][3] + Dh * fX[lb * 68 + p0 + 1];
            }
        }
        {
            float pt = dsm[OFF_SC + 256];
#pragma unroll
            for (int n8 = 0; n8 < 4; n8++)
#pragma unroll
                for (int r = 0; r < 4; r++) Sreg[n8][r] *= pt;
#pragma unroll
            for (int k8 = 0; k8 < 8; k8++) {
                int kc = k8 * 8;
                float a[4];
                a[0] = fX[(kc + tg) * 68 + pm + g];
                a[1] = fX[(kc + tg) * 68 + pm + g + 8];
                a[2] = fX[(kc + tg + 4) * 68 + pm + g];
                a[3] = fX[(kc + tg + 4) * 68 + pm + g + 8];
#pragma unroll
                for (int n8 = 0; n8 < 4; n8++) {
                    int n = nh + n8 * 8 + g;
                    float bv[2];
                    bv[0] = dsm[OFF_BW + (kc + tg) * 68 + n];
                    bv[1] = dsm[OFF_BW + (kc + tg + 4) * 68 + n];
                    mma1s(Sreg[n8], a, bv);
                }
            }
        }
        __syncthreads();
#pragma unroll
        for (int n8 = 0; n8 < 4; n8++) {
            int n0 = nh + n8 * 8 + 2 * tg;
            dsm[OFF_S + (pm + g) * 68 + n0]         = tf32r(Sreg[n8][0]);
            dsm[OFF_S + (pm + g) * 68 + n0 + 1]     = tf32r(Sreg[n8][1]);
            dsm[OFF_S + (pm + g + 8) * 68 + n0]     = tf32r(Sreg[n8][2]);
            dsm[OFF_S + (pm + g + 8) * 68 + n0 + 1] = tf32r(Sreg[n8][3]);
        }
    }
}

// ------ fused gate + rms, warp-per-row: y = rmsnorm(y*silu(z)) * rms_w ------
// 8 warps/block, each warp owns one (b,l) row; pure shfl reduction, no smem.
__global__ void __launch_bounds__(256) gate_rms_k(const float* __restrict__ rmsw)
{
    int w = threadIdx.x >> 5, lane = threadIdx.x & 31;
    size_t row = (size_t)blockIdx.x * 8 + w;
    float4* y4 = (float4*)(g_y + row * D_INNER);
    const float4* z4 = (const float4*)(g_zx + row * D_IN_PROJ);
    float4 gv[4];
    float ss = 0.f;
#pragma unroll
    for (int i = 0; i < 4; i++) {
        float4 yv = y4[lane + i * 32];
        float4 zv = z4[lane + i * 32];
        float4 g;
        g.x = yv.x * (zv.x / (1.f + __expf(-zv.x)));
        g.y = yv.y * (zv.y / (1.f + __expf(-zv.y)));
        g.z = yv.z * (zv.z / (1.f + __expf(-zv.z)));
        g.w = yv.w * (zv.w / (1.f + __expf(-zv.w)));
        gv[i] = g;
        ss += g.x * g.x + g.y * g.y + g.z * g.z + g.w * g.w;
    }
#pragma unroll
    for (int o = 16; o > 0; o >>= 1) ss += __shfl_xor_sync(0xffffffffu, ss, o);
    float sc = rsqrtf(ss * (1.f / 512.f) + 1e-5f);
#pragma unroll
    for (int i = 0; i < 4; i++) {
        float4 wv = ((const float4*)rmsw)[lane + i * 32];
        float4 o;
        o.x = gv[i].x * sc * wv.x;
        o.y = gv[i].y * sc * wv.y;
        o.z = gv[i].z * sc * wv.z;
        o.w = gv[i].w * sc * wv.w;
        y4[lane + i * 32] = o;
    }
}

// ---------------- final LayerNorm (per row) + partial mean over l -----------
__global__ void __launch_bounds__(256) ln_part_k()
{
    __shared__ float sb[8];
    int b = blockIdx.x;
    int chunk = blockIdx.y;
    int c = threadIdx.x;
    int lane = c & 31, wid = c >> 5;
    float acc = 0.f;
    for (int i = 0; i < 64; i++) {
        int l = chunk * 64 + i;
        float v = g_h[((size_t)(b * NL + l)) * D_MODEL + c];
        float s = v;
#pragma unroll
        for (int o = 16; o > 0; o >>= 1) s += __shfl_xor_sync(0xffffffffu, s, o);
        if (lane == 0) sb[wid] = s;
        __syncthreads();
        float tot = sb[0] + sb[1] + sb[2] + sb[3] + sb[4] + sb[5] + sb[6] + sb[7];
        __syncthreads();
        float mu = tot * (1.f / 256.f);
        float d = v - mu;
        float s2 = d * d;
#pragma unroll
        for (int o = 16; o > 0; o >>= 1) s2 += __shfl_xor_sync(0xffffffffu, s2, o);
        if (lane == 0) sb[wid] = s2;
        __syncthreads();
        float var = (sb[0] + sb[1] + sb[2] + sb[3] + sb[4] + sb[5] + sb[6] + sb[7]) * (1.f / 256.f);
        __syncthreads();
        acc += d * rsqrtf(var + 1e-5f);
    }
    g_part[((size_t)(b * 32 + chunk)) * D_MODEL + c] = acc;
}

// ---------------- reduce partials, apply LN affine, compute heads -----------
__global__ void __launch_bounds__(256) final_k(
    const float* __restrict__ lnw, const float* __restrict__ lnb,
    const float* __restrict__ dirw, const float* __restrict__ dirb,
    const float* __restrict__ regw, const float* __restrict__ regb,
    float* __restrict__ out)
{
    __shared__ float hb[NB * D_MODEL];
    int t = threadIdx.x;
#pragma unroll
    for (int i = 0; i < (NB * D_MODEL) / 256; i++) {
        int idx = t + i * 256;
        int c = idx & 255;
        int bb = idx >> 8;
        float s = 0.f;
#pragma unroll
        for (int j = 0; j < 32; j++)
            s += g_part[((size_t)(bb * 32 + j)) * D_MODEL + c];
        hb[idx] = s * (1.f / 2048.f) * lnw[c] + lnb[c];
    }
    __syncthreads();
    if (t < NB) {
        float s = dirb[0];
        for (int c = 0; c < D_MODEL; c++) s += hb[t * D_MODEL + c] * dirw[c];
        out[t] = s;
    } else if (t < NB + NB * 3) {
        int q = t - NB;
        int bb = q / 3, j = q % 3;
        float s = regb[j];
        for (int c = 0; c < D_MODEL; c++) s += hb[bb * D_MODEL + c] * regw[c * 3 + j];
        out[NB + q] = s;
    }
}

// ---------------- launch ----------------------------------------------------
extern "C" void kernel_launch(void* const* d_in, const int* in_sizes, int n_in,
                              void* d_out, int out_size)
{
    const float* x    = (const float*)d_in[0];
    const float* inpw = (const float*)d_in[1];
    const float* inpb = (const float*)d_in[2];
    const float* ipw  = (const float*)d_in[3];
    const float* cw   = (const float*)d_in[4];
    const float* cb   = (const float*)d_in[5];
    const float* dtb  = (const float*)d_in[6];
    const float* alog = (const float*)d_in[7];
    const float* Dp   = (const float*)d_in[8];
    const float* rmsw = (const float*)d_in[9];
    const float* opw  = (const float*)d_in[10];
    const float* lnw  = (const float*)d_in[11];
    const float* lnb  = (const float*)d_in[12];
    const float* dirw = (const float*)d_in[13];
    const float* dirb = (const float*)d_in[14];
    const float* regw = (const float*)d_in[15];
    const float* regb = (const float*)d_in[16];
    float* out = (float*)d_out;

    void *ph_, *pzx_, *py_;
    cudaGetSymbolAddress(&ph_,  g_h);
    cudaGetSymbolAddress(&pzx_, g_zx);
    cudaGetSymbolAddress(&py_,  g_y);
    float* ph  = (float*)ph_;
    float* pzx = (float*)pzx_;
    float* py  = (float*)py_;

    cudaFuncSetAttribute(scan_k, cudaFuncAttributeMaxDynamicSharedMemorySize,
                         SCAN_SMEM_BYTES);

    // h = x @ inp_w + inp_b            [32768 x 256, K=46]  (fp32, tiny)
    sgemm_k<<<dim3(D_MODEL / 64, BL / 64), 128>>>(x, inpw, inpb, ph, BL, D_MODEL, NF, 0);

    const int convdt_threads = (BL / 8) * (CONV_DIM / 4) + BL * NHEADS;

    for (int i = 0; i < N_LAYERS; i++) {
        // zxbcdt = h @ in_proj_w       [32768 x 1160, K=256]  (tf32 tensor)
        tf32gemm_k<<<dim3((D_IN_PROJ + 63) / 64, BL / 128), 256>>>(
            ph, ipw + (size_t)i * D_MODEL * D_IN_PROJ, pzx,
            BL, D_IN_PROJ, D_MODEL, 0);
        // conv + silu (tf32-rounded, register-shifted) + (dtA, dt) precompute
        convdt_k<<<(convdt_threads + 255) / 256, 256>>>(
            cw + (size_t)i * CONV_DIM * 4, cb + (size_t)i * CONV_DIM,
            dtb + i * NHEADS, alog + i * NHEADS);
        // chunked SSD scan (+ D*x skip), CHUNK=64, single-pass tf32
        scan_k<<<NB * NHEADS, 256, SCAN_SMEM_BYTES>>>(Dp + i * NHEADS);
        // y = rmsnorm(y * silu(z)) * rms_w  (warp-per-row, fused)
        gate_rms_k<<<BL / 8, 256>>>(rmsw + (size_t)i * D_INNER);
        // h += y @ out_proj_w          [32768 x 256, K=512]  (tf32 tensor, accumulate)
        tf32gemm_k<<<dim3(D_MODEL / 64, BL / 128), 256>>>(
            py, opw + (size_t)i * D_INNER * D_MODEL, ph,
            BL, D_MODEL, D_INNER, 1);
    }

    ln_part_k<<<dim3(NB, 32), 256>>>();
    final_k<<<1, 256>>>(lnw, lnb, dirw, dirb, regw, regb, out);
}

// round 14
// speedup vs baseline: 1.0544x; 1.0274x over previous
#include <cuda_runtime.h>
#include <cstdint>

#define NB 16
#define NL 2048
#define NF 46
#define D_MODEL 256
#define D_INNER 512
#define D_STATE 64
#define NHEADS 8
#define HEADDIM 64
#define CONV_DIM 640
#define D_IN_PROJ 1160
#define N_LAYERS 4
#define BL (NB*NL)
#define CHUNK 64
#define NCHUNK (NL/CHUNK)

#define IPW_ELEMS (N_LAYERS * D_MODEL * D_IN_PROJ)   // 1,187,840
#define OPW_ELEMS (N_LAYERS * D_INNER * D_MODEL)     //   524,288

// ---------------- scratch (static device globals; no runtime allocation) ----
__device__ float g_h[(size_t)BL * D_MODEL];      // residual stream
__device__ float g_zx[(size_t)BL * D_IN_PROJ];   // in_proj output
__device__ float g_xc[(size_t)BL * CONV_DIM];    // conv+silu output (tf32-rounded)
__device__ float g_sd[(size_t)BL * NHEADS * 2];  // (dtA, dt) pairs, [b*8+h][l]
__device__ float g_y[(size_t)BL * D_INNER];      // scan output / gated-norm
__device__ float g_part[NB * 32 * D_MODEL];      // LN partial sums
__device__ float g_wr[IPW_ELEMS + OPW_ELEMS];    // tf32-pre-rounded weights

// ---------------- tf32 / cp.async helpers ------------------------------------
__device__ __forceinline__ uint32_t to_tf32(float x) {
    uint32_t r;
    asm("cvt.rna.tf32.f32 %0, %1;" : "=r"(r) : "f"(x));
    return r;
}
__device__ __forceinline__ float tf32r(float x) {
    return __uint_as_float(to_tf32(x));
}
__device__ __forceinline__ void cpa16(void* dst, const void* src) {
    uint32_t d = (uint32_t)__cvta_generic_to_shared(dst);
    asm volatile("cp.async.cg.shared.global [%0], [%1], 16;" :: "r"(d), "l"(src));
}
__device__ __forceinline__ void cpa16z(void* dst, const void* src, int bytes) {
    uint32_t d = (uint32_t)__cvta_generic_to_shared(dst);
    asm volatile("cp.async.cg.shared.global [%0], [%1], 16, %2;"
                 :: "r"(d), "l"(src), "r"(bytes));
}
__device__ __forceinline__ void cpa_commit() { asm volatile("cp.async.commit_group;"); }
__device__ __forceinline__ void cpa_wait0()  { asm volatile("cp.async.wait_group 0;"); }
__device__ __forceinline__ void cpa_wait1()  { asm volatile("cp.async.wait_group 1;"); }

__device__ __forceinline__ void mma_tf32(float c[4], const uint32_t a[4], const uint32_t b[2]) {
    asm volatile(
        "mma.sync.aligned.m16n8k8.row.col.f32.tf32.tf32.f32 "
        "{%0,%1,%2,%3}, {%4,%5,%6,%7}, {%8,%9}, {%0,%1,%2,%3};"
        : "+f"(c[0]), "+f"(c[1]), "+f"(c[2]), "+f"(c[3])
        : "r"(a[0]), "r"(a[1]), "r"(a[2]), "r"(a[3]), "r"(b[0]), "r"(b[1]));
}
// single-pass mma from pre-rounded fp32 smem values
__device__ __forceinline__ void mma1s(float c[4], const float a[4], const float b[2]) {
    uint32_t A[4] = {__float_as_uint(a[0]), __float_as_uint(a[1]),
                     __float_as_uint(a[2]), __float_as_uint(a[3])};
    uint32_t B[2] = {__float_as_uint(b[0]), __float_as_uint(b[1])};
    mma_tf32(c, A, B);
}

// ---------------- weight pre-round: g_wr = tf32(ipw ++ opw) ------------------
__global__ void __launch_bounds__(256) roundw_k(
    const float* __restrict__ ipw, const float* __restrict__ opw)
{
    int i4 = blockIdx.x * 256 + threadIdx.x;
    const int totq = (IPW_ELEMS + OPW_ELEMS) / 4;
    if (i4 >= totq) return;
    int e = i4 * 4;
    float4 v = (e < IPW_ELEMS) ? *(const float4*)(ipw + e)
                               : *(const float4*)(opw + (e - IPW_ELEMS));
    float4 o;
    o.x = tf32r(v.x); o.y = tf32r(v.y); o.z = tf32r(v.z); o.w = tf32r(v.w);
    *(float4*)(g_wr + e) = o;
}

// ---------------- tf32 tensor-core GEMM: BM=128,BN=64,BK=16 ------------------
// B must be tf32-pre-rounded (bit-loaded); A is cvt.rna'd in-loop (unchanged).
__global__ void __launch_bounds__(256) tf32gemm_k(
    const float* __restrict__ A, const float* __restrict__ B,
    float* __restrict__ C, int M, int N, int K, int acc_flag)
{
    __shared__ __align__(16) float As[3][128][20];
    __shared__ __align__(16) float Bs[3][16][72];

    const int tid  = threadIdx.x;
    const int bm   = blockIdx.y * 128;
    const int bn   = blockIdx.x * 64;
    const int warp = tid >> 5, lane = tid & 31;
    const int wm   = (warp >> 1) * 32;
    const int wn   = (warp & 1) * 32;
    const int g    = lane >> 2;
    const int tg   = lane & 3;

    float acc[2][4][4];
#pragma unroll
    for (int mt = 0; mt < 2; mt++)
#pragma unroll
        for (int nt = 0; nt < 4; nt++)
#pragma unroll
            for (int i = 0; i < 4; i++) acc[mt][nt][i] = 0.f;

    const int KT = K >> 4;
    const int b_k  = tid >> 4;
    const int b_nq = (tid & 15) * 4;

    auto load_stage = [&](int s, int k0) {
#pragma unroll
        for (int i = 0; i < 2; i++) {
            int idx = tid * 2 + i;
            int m = idx >> 2, kq = (idx & 3) * 4;
            cpa16(&As[s][m][kq], A + (size_t)(bm + m) * K + k0 + kq);
        }
        {
            int n = bn + b_nq;
            int nc = n < N - 4 ? n : N - 4;
            int bytes = (n < N) ? ((N - n) * 4 < 16 ? (N - n) * 4 : 16) : 0;
            cpa16z(&Bs[s][b_k][b_nq], B + (size_t)(k0 + b_k) * N + nc, bytes);
        }
        cpa_commit();
    };

    load_stage(0, 0);
    if (KT > 1) load_stage(1, 16);

    for (int kt = 0; kt < KT; kt++) {
        cpa_wait1();
        __syncthreads();
        if (kt + 2 < KT) load_stage((kt + 2) % 3, (kt + 2) * 16);
        const int s = kt % 3;
#pragma unroll
        for (int ks = 0; ks < 2; ks++) {
            uint32_t af[2][4];
#pragma unroll
            for (int mt = 0; mt < 2; mt++) {
                int r = wm + mt * 16 + g;
                int c = ks * 8 + tg;
                af[mt][0] = to_tf32(As[s][r][c]);
                af[mt][1] = to_tf32(As[s][r + 8][c]);
                af[mt][2] = to_tf32(As[s][r][c + 4]);
                af[mt][3] = to_tf32(As[s][r + 8][c + 4]);
            }
            uint32_t bf[4][2];
#pragma unroll
            for (int nt = 0; nt < 4; nt++) {
                int col = wn + nt * 8 + g;
                bf[nt][0] = __float_as_uint(Bs[s][ks * 8 + tg][col]);
                bf[nt][1] = __float_as_uint(Bs[s][ks * 8 + tg + 4][col]);
            }
#pragma unroll
            for (int mt = 0; mt < 2; mt++)
#pragma unroll
                for (int nt = 0; nt < 4; nt++)
                    mma_tf32(acc[mt][nt], af[mt], bf[nt]);
        }
    }

#pragma unroll
    for (int mt = 0; mt < 2; mt++) {
        int r0 = bm + wm + mt * 16 + g;
#pragma unroll
        for (int nt = 0; nt < 4; nt++) {
            int col = bn + wn + nt * 8 + 2 * tg;
            if (col < N) {
                size_t o0 = (size_t)r0 * N + col;
                size_t o1 = (size_t)(r0 + 8) * N + col;
                if (acc_flag) {
                    C[o0]     += acc[mt][nt][0];
                    C[o0 + 1] += acc[mt][nt][1];
                    C[o1]     += acc[mt][nt][2];
                    C[o1 + 1] += acc[mt][nt][3];
                } else {
                    C[o0]     = acc[mt][nt][0];
                    C[o0 + 1] = acc[mt][nt][1];
                    C[o1]     = acc[mt][nt][2];
                    C[o1 + 1] = acc[mt][nt][3];
                }
            }
        }
    }
}

// ---------------- fp32 tiled SGEMM (tiny K=46 input GEMM) -------------------
__global__ void __launch_bounds__(128) sgemm_k(
    const float* __restrict__ A, const float* __restrict__ B,
    const float* __restrict__ bias, float* __restrict__ C,
    int M, int N, int K, int acc_flag)
{
    __shared__ __align__(16) float As[16][68];
    __shared__ __align__(16) float Bs[16][64];
    const int bm = blockIdx.y * 64;
    const int bn = blockIdx.x * 64;
    const int tid = threadIdx.x;
    const int tx = tid & 7;
    const int ty = tid >> 3;
    const int aRow = tid >> 4;
    const int aCol = tid & 15;
    const int bRow = tid >> 6;
    const int bCol = tid & 63;

    float acc[4][8];
#pragma unroll
    for (int i = 0; i < 4; i++)
#pragma unroll
        for (int j = 0; j < 8; j++) acc[i][j] = 0.f;

    for (int k0 = 0; k0 < K; k0 += 16) {
#pragma unroll
        for (int i = 0; i < 8; i++) {
            int m = bm + aRow + 8 * i;
            int k = k0 + aCol;
            As[aCol][aRow + 8 * i] = (k < K) ? A[(size_t)m * K + k] : 0.f;
        }
#pragma unroll
        for (int i = 0; i < 8; i++) {
            int k = k0 + bRow + 2 * i;
            int n = bn + bCol;
            Bs[bRow + 2 * i][bCol] = (k < K && n < N) ? B[(size_t)k * N + n] : 0.f;
        }
        __syncthreads();
#pragma unroll
        for (int k = 0; k < 16; k++) {
            float4 a4  = *(const float4*)&As[k][ty * 4];
            float4 b4a = *(const float4*)&Bs[k][tx * 8];
            float4 b4b = *(const float4*)&Bs[k][tx * 8 + 4];
            float a[4]  = {a4.x, a4.y, a4.z, a4.w};
            float bb[8] = {b4a.x, b4a.y, b4a.z, b4a.w, b4b.x, b4b.y, b4b.z, b4b.w};
#pragma unroll
            for (int i = 0; i < 4; i++)
#pragma unroll
                for (int j = 0; j < 8; j++)
                    acc[i][j] = fmaf(a[i], bb[j], acc[i][j]);
        }
        __syncthreads();
    }
#pragma unroll
    for (int i = 0; i < 4; i++) {
        int m = bm + ty * 4 + i;
#pragma unroll
        for (int j = 0; j < 8; j++) {
            int n = bn + tx * 8 + j;
            if (n < N) {
                float v = acc[i][j];
                if (bias) v += bias[n];
                size_t off = (size_t)m * N + n;
                if (acc_flag) v += C[off];
                C[off] = v;
            }
        }
    }
}

// -------- fused: depthwise conv(k=4)+bias+silu v2 (8 tok x 4 ch / thread) ---
__global__ void __launch_bounds__(256) convdt_k(
    const float* __restrict__ cw, const float* __restrict__ cb,
    const float* __restrict__ dtb, const float* __restrict__ Alog)
{
    const int CG = CONV_DIM / 4;              // 160 channel-groups
    const int convN = (BL / 8) * CG;          // 655,360 (multiple of 256)
    int idx = blockIdx.x * 256 + threadIdx.x;
    if (idx < convN) {
        int blg = idx / CG, cg = idx - blg * CG;
        int bl0 = blg * 8;                    // 8 tokens, never crosses batch
        int l0  = bl0 & (NL - 1);
        int c   = cg * 4;
        const float* base = g_zx + (size_t)bl0 * D_IN_PROJ + 512 + c;

        float4 v[11];
#pragma unroll
        for (int i = 0; i < 11; i++) {
            int off = i - 3;
            if (l0 + off >= 0)
                v[i] = *(const float4*)(base + (ptrdiff_t)off * D_IN_PROJ);
            else
                v[i] = make_float4(0.f, 0.f, 0.f, 0.f);
        }
        float4 w0 = *(const float4*)(cw + (size_t)(c + 0) * 4);
        float4 w1 = *(const float4*)(cw + (size_t)(c + 1) * 4);
        float4 w2 = *(const float4*)(cw + (size_t)(c + 2) * 4);
        float4 w3 = *(const float4*)(cw + (size_t)(c + 3) * 4);
        float4 bb = *(const float4*)(cb + c);
        const float wk0[4] = {w0.x, w0.y, w0.z, w0.w};
        const float wk1[4] = {w1.x, w1.y, w1.z, w1.w};
        const float wk2[4] = {w2.x, w2.y, w2.z, w2.w};
        const float wk3[4] = {w3.x, w3.y, w3.z, w3.w};

        float* outp = g_xc + (size_t)bl0 * CONV_DIM + c;
#pragma unroll
        for (int i = 0; i < 8; i++) {
            float a0 = bb.x, a1 = bb.y, a2 = bb.z, a3 = bb.w;
#pragma unroll
            for (int k = 0; k < 4; k++) {
                a0 = fmaf(v[i + k].x, wk0[k], a0);
                a1 = fmaf(v[i + k].y, wk1[k], a1);
                a2 = fmaf(v[i + k].z, wk2[k], a2);
                a3 = fmaf(v[i + k].w, wk3[k], a3);
            }
            float4 o;
            o.x = tf32r(a0 / (1.f + __expf(-a0)));
            o.y = tf32r(a1 / (1.f + __expf(-a1)));
            o.z = tf32r(a2 / (1.f + __expf(-a2)));
            o.w = tf32r(a3 / (1.f + __expf(-a3)));
            *(float4*)(outp + (size_t)i * CONV_DIM) = o;
        }
    } else {
        int j = idx - convN;
        if (j < BL * NHEADS) {
            int l  = j & (NL - 1);
            int bh = j >> 11;
            int b  = bh >> 3;
            int h  = bh & 7;
            float v = g_zx[((size_t)(b * NL + l)) * D_IN_PROJ + 1152 + h] + dtb[h];
            float dt = (v > 20.f) ? v : log1pf(expf(v));
            float dtA = dt * (-__expf(Alog[h]));
            ((float2*)g_sd)[j] = make_float2(dtA, dt);
        }
    }
}

// ---------------- scan v8: chunked SSD, CHUNK=64, triangle skips -------------
#define OFF_F    0                       // stage [2 buf][3 tile][64][68] (X,B,C)
#define SZ_TILE  4352                    // 64*68
#define SZ_FBUF  (3*SZ_TILE)             // 13056
#define OFF_W    (2*SZ_FBUF)             // W [64][68]
#define OFF_BW   (OFF_W + SZ_TILE)       // Bw [64][68]
#define OFF_S    (OFF_BW + SZ_TILE)      // S mirror [64][68]
#define OFF_SD   (OFF_S + SZ_TILE)       // (dtA,dt) [2 buf][64 float2]
#define OFF_SC   (OFF_SD + 256)          // s_s[64],s_dt[64],s_wq[64],s_el[64],ptot
#define SCAN_SMEM_FLOATS (OFF_SC + 260)
#define SCAN_SMEM_BYTES  (SCAN_SMEM_FLOATS * 4)

__global__ void __launch_bounds__(256) scan_k(const float* __restrict__ Dp)
{
    extern __shared__ __align__(16) float dsm[];

    const int bh = blockIdx.x;
    const int b = bh >> 3, h = bh & 7;
    const int t = threadIdx.x;
    const int w = t >> 5, lane = t & 31;
    const int g = lane >> 2, tg = lane & 3;
    const float Dh = Dp[h];

    const float* xcb = g_xc + (size_t)b * NL * CONV_DIM;
    const float* sdp = g_sd + (size_t)bh * NL * 2;

    float* s_s  = dsm + OFF_SC;
    float* s_dt = dsm + OFF_SC + 64;
    float* s_wq = dsm + OFF_SC + 128;
    float* s_el = dsm + OFF_SC + 192;

    for (int i = t; i < SZ_TILE; i += 256) dsm[OFF_S + i] = 0.f;

    float Sreg[4][4];
#pragma unroll
    for (int i = 0; i < 4; i++)
#pragma unroll
        for (int r = 0; r < 4; r++) Sreg[i][r] = 0.f;

    auto stage = [&](int buf, int l0) {
        float* fb = dsm + OFF_F + buf * SZ_FBUF;
#pragma unroll
        for (int i = 0; i < 12; i++) {
            int slot = t + i * 256;
            int tile = slot >> 10;
            int rc = slot & 1023;
            int row = rc >> 4, c4 = (rc & 15) * 4;
            const float* src = xcb + (size_t)(l0 + row) * CONV_DIM;
            const int goff = (tile == 0) ? h * HEADDIM : (tile == 1 ? 512 : 576);
            cpa16(fb + tile * SZ_TILE + row * 68 + c4, src + goff + c4);
        }
        if (t < 32)
            cpa16(dsm + OFF_SD + buf * 128 + t * 4, sdp + (size_t)l0 * 2 + t * 4);
        cpa_commit();
    };

    stage(0, 0);

    const int mb = (w & 3) * 16, c0 = (w >> 2) * 32;
    const int pm = mb, nh = c0;

    for (int ch = 0; ch < NCHUNK; ch++) {
        const int buf = ch & 1;
        const int l0 = ch * CHUNK;
        const float* fX = dsm + OFF_F + buf * SZ_FBUF;
        const float* fB = fX + SZ_TILE;
        const float* fC = fB + SZ_TILE;

        cpa_wait0();
        __syncthreads();

        if (ch + 1 < NCHUNK) stage(buf ^ 1, l0 + CHUNK);

        if (w == 0) {
            const float2* sd2 = (const float2*)(dsm + OFF_SD + buf * 128);
            float2 ua = sd2[2 * lane];
            float2 ub = sd2[2 * lane + 1];
            float ps = ua.x + ub.x;
            float sc_ = ps;
#pragma unroll
            for (int o = 1; o < 32; o <<= 1) {
                float v = __shfl_up_sync(0xffffffffu, sc_, o);
                if (lane >= o) sc_ += v;
            }
            float stot = __shfl_sync(0xffffffffu, sc_, 31);
            float s1 = sc_;
            float s0 = sc_ - ub.x;
            s_s[2 * lane]      = s0;
            s_s[2 * lane + 1]  = s1;
            s_dt[2 * lane]     = ua.y;
            s_dt[2 * lane + 1] = ub.y;
            s_wq[2 * lane]     = __expf(stot - s0) * ua.y;
            s_wq[2 * lane + 1] = __expf(stot - s1) * ub.y;
            s_el[2 * lane]     = __expf(s0);
            s_el[2 * lane + 1] = __expf(s1);
            if (lane == 31) dsm[OFF_SC + 256] = __expf(stot);
        }

        float Gacc[4][4] = {{0,0,0,0},{0,0,0,0},{0,0,0,0},{0,0,0,0}};
        if (mb + 15 >= c0) {
#pragma unroll
            for (int k8 = 0; k8 < 8; k8++) {
                int kc = k8 * 8;
                float a[4];
                a[0] = fC[(mb + g) * 68 + kc + tg];
                a[1] = fC[(mb + g + 8) * 68 + kc + tg];
                a[2] = fC[(mb + g) * 68 + kc + tg + 4];
                a[3] = fC[(mb + g + 8) * 68 + kc + tg + 4];
#pragma unroll
                for (int n8 = 0; n8 < 4; n8++) {
                    if (mb + 15 >= c0 + n8 * 8) {
                        float bv[2];
                        bv[0] = fB[(c0 + n8 * 8 + g) * 68 + kc + tg];
                        bv[1] = fB[(c0 + n8 * 8 + g) * 68 + kc + tg + 4];
                        mma1s(Gacc[n8], a, bv);
                    }
                }
            }
        }
        __syncthreads();

        {
            int la = mb + g, lb = la + 8;
#pragma unroll
            for (int n8 = 0; n8 < 4; n8++) {
                int ja = c0 + n8 * 8 + 2 * tg, jb2 = ja + 1;
                float w0_ = (la >= ja)  ? Gacc[n8][0] * __expf(s_s[la] - s_s[ja])  * s_dt[ja]  : 0.f;
                float w1_ = (la >= jb2) ? Gacc[n8][1] * __expf(s_s[la] - s_s[jb2]) * s_dt[jb2] : 0.f;
                float w2_ = (lb >= ja)  ? Gacc[n8][2] * __expf(s_s[lb] - s_s[ja])  * s_dt[ja]  : 0.f;
                float w3_ = (lb >= jb2) ? Gacc[n8][3] * __expf(s_s[lb] - s_s[jb2]) * s_dt[jb2] : 0.f;
                dsm[OFF_W + la * 68 + ja]  = tf32r(w0_);
                dsm[OFF_W + la * 68 + jb2] = tf32r(w1_);
                dsm[OFF_W + lb * 68 + ja]  = tf32r(w2_);
                dsm[OFF_W + lb * 68 + jb2] = tf32r(w3_);
            }
        }
#pragma unroll
        for (int i = 0; i < 16; i++) {
            int idx = t + i * 256;
            int r = idx >> 6, c = idx & 63;
            dsm[OFF_BW + r * 68 + c] = tf32r(s_wq[r] * fB[r * 68 + c]);
        }
        __syncthreads();

        float Y[4][4] = {{0,0,0,0},{0,0,0,0},{0,0,0,0},{0,0,0,0}};
#pragma unroll
        for (int k8 = 0; k8 < 8; k8++) {
            int kc = k8 * 8;
            if (kc > mb + 15) break;
            float a[4];
            a[0] = dsm[OFF_W + (mb + g) * 68 + kc + tg];
            a[1] = dsm[OFF_W + (mb + g + 8) * 68 + kc + tg];
            a[2] = dsm[OFF_W + (mb + g) * 68 + kc + tg + 4];
            a[3] = dsm[OFF_W + (mb + g + 8) * 68 + kc + tg + 4];
#pragma unroll
            for (int n8 = 0; n8 < 4; n8++) {
                int p = c0 + n8 * 8 + g;
                float bv[2];
                bv[0] = fX[(kc + tg) * 68 + p];
                bv[1] = fX[(kc + tg + 4) * 68 + p];
                mma1s(Y[n8], a, bv);
            }
        }
        float Y3[4][4] = {{0,0,0,0},{0,0,0,0},{0,0,0,0},{0,0,0,0}};
#pragma unroll
        for (int k8 = 0; k8 < 8; k8++) {
            int kc = k8 * 8;
            float a[4];
            a[0] = fC[(mb + g) * 68 + kc + tg];
            a[1] = fC[(mb + g + 8) * 68 + kc + tg];
            a[2] = fC[(mb + g) * 68 + kc + tg + 4];
            a[3] = fC[(mb + g + 8) * 68 + kc + tg + 4];
#pragma unroll
            for (int n8 = 0; n8 < 4; n8++) {
                int p = c0 + n8 * 8 + g;
                float bv[2];
                bv[0] = dsm[OFF_S + p * 68 + kc + tg];
                bv[1] = dsm[OFF_S + p * 68 + kc + tg + 4];
                mma1s(Y3[n8], a, bv);
            }
        }
        {
            float e0 = s_el[mb + g], e1 = s_el[mb + g + 8];
#pragma unroll
            for (int n8 = 0; n8 < 4; n8++) {
                Y[n8][0] = fmaf(e0, Y3[n8][0], Y[n8][0]);
                Y[n8][1] = fmaf(e0, Y3[n8][1], Y[n8][1]);
                Y[n8][2] = fmaf(e1, Y3[n8][2], Y[n8][2]);
                Y[n8][3] = fmaf(e1, Y3[n8][3], Y[n8][3]);
            }
        }
        {
            int la = mb + g, lb = la + 8;
            float* ya_ = g_y + ((size_t)(b * NL + l0 + la)) * D_INNER + h * HEADDIM;
            float* yb_ = g_y + ((size_t)(b * NL + l0 + lb)) * D_INNER + h * HEADDIM;
#pragma unroll
            for (int n8 = 0; n8 < 4; n8++) {
                int p0 = c0 + n8 * 8 + 2 * tg;
                ya_[p0]     = Y[n8][0] + Dh * fX[la * 68 + p0];
                ya_[p0 + 1] = Y[n8][1] + Dh * fX[la * 68 + p0 + 1];
                yb_[p0]     = Y[n8][2] + Dh * fX[lb * 68 + p0];
                yb_[p0 + 1] = Y[n8][3] + Dh * fX[lb * 68 + p0 + 1];
            }
        }
        {
            float pt = dsm[OFF_SC + 256];
#pragma unroll
            for (int n8 = 0; n8 < 4; n8++)
#pragma unroll
                for (int r = 0; r < 4; r++) Sreg[n8][r] *= pt;
#pragma unroll
            for (int k8 = 0; k8 < 8; k8++) {
                int kc = k8 * 8;
                float a[4];
                a[0] = fX[(kc + tg) * 68 + pm + g];
                a[1] = fX[(kc + tg) * 68 + pm + g + 8];
                a[2] = fX[(kc + tg + 4) * 68 + pm + g];
                a[3] = fX[(kc + tg + 4) * 68 + pm + g + 8];
#pragma unroll
                for (int n8 = 0; n8 < 4; n8++) {
                    int n = nh + n8 * 8 + g;
                    float bv[2];
                    bv[0] = dsm[OFF_BW + (kc + tg) * 68 + n];
                    bv[1] = dsm[OFF_BW + (kc + tg + 4) * 68 + n];
                    mma1s(Sreg[n8], a, bv);
                }
            }
        }
        __syncthreads();
#pragma unroll
        for (int n8 = 0; n8 < 4; n8++) {
            int n0 = nh + n8 * 8 + 2 * tg;
            dsm[OFF_S + (pm + g) * 68 + n0]         = tf32r(Sreg[n8][0]);
            dsm[OFF_S + (pm + g) * 68 + n0 + 1]     = tf32r(Sreg[n8][1]);
            dsm[OFF_S + (pm + g + 8) * 68 + n0]     = tf32r(Sreg[n8][2]);
            dsm[OFF_S + (pm + g + 8) * 68 + n0 + 1] = tf32r(Sreg[n8][3]);
        }
    }
}

// ------ fused gate + rms, warp-per-row: y = rmsnorm(y*silu(z)) * rms_w ------
__global__ void __launch_bounds__(256) gate_rms_k(const float* __restrict__ rmsw)
{
    int w = threadIdx.x >> 5, lane = threadIdx.x & 31;
    size_t row = (size_t)blockIdx.x * 8 + w;
    float4* y4 = (float4*)(g_y + row * D_INNER);
    const float4* z4 = (const float4*)(g_zx + row * D_IN_PROJ);
    float4 gv[4];
    float ss = 0.f;
#pragma unroll
    for (int i = 0; i < 4; i++) {
        float4 yv = y4[lane + i * 32];
        float4 zv = z4[lane + i * 32];
        float4 g;
        g.x = yv.x * (zv.x / (1.f + __expf(-zv.x)));
        g.y = yv.y * (zv.y / (1.f + __expf(-zv.y)));
        g.z = yv.z * (zv.z / (1.f + __expf(-zv.z)));
        g.w = yv.w * (zv.w / (1.f + __expf(-zv.w)));
        gv[i] = g;
        ss += g.x * g.x + g.y * g.y + g.z * g.z + g.w * g.w;
    }
#pragma unroll
    for (int o = 16; o > 0; o >>= 1) ss += __shfl_xor_sync(0xffffffffu, ss, o);
    float sc = rsqrtf(ss * (1.f / 512.f) + 1e-5f);
#pragma unroll
    for (int i = 0; i < 4; i++) {
        float4 wv = ((const float4*)rmsw)[lane + i * 32];
        float4 o;
        o.x = gv[i].x * sc * wv.x;
        o.y = gv[i].y * sc * wv.y;
        o.z = gv[i].z * sc * wv.z;
        o.w = gv[i].w * sc * wv.w;
        y4[lane + i * 32] = o;
    }
}

// ---------------- final LayerNorm (per row) + partial mean over l -----------
__global__ void __launch_bounds__(256) ln_part_k()
{
    __shared__ float sb[8];
    int b = blockIdx.x;
    int chunk = blockIdx.y;
    int c = threadIdx.x;
    int lane = c & 31, wid = c >> 5;
    float acc = 0.f;
    for (int i = 0; i < 64; i++) {
        int l = chunk * 64 + i;
        float v = g_h[((size_t)(b * NL + l)) * D_MODEL + c];
        float s = v;
#pragma unroll
        for (int o = 16; o > 0; o >>= 1) s += __shfl_xor_sync(0xffffffffu, s, o);
        if (lane == 0) sb[wid] = s;
        __syncthreads();
        float tot = sb[0] + sb[1] + sb[2] + sb[3] + sb[4] + sb[5] + sb[6] + sb[7];
        __syncthreads();
        float mu = tot * (1.f / 256.f);
        float d = v - mu;
        float s2 = d * d;
#pragma unroll
        for (int o = 16; o > 0; o >>= 1) s2 += __shfl_xor_sync(0xffffffffu, s2, o);
        if (lane == 0) sb[wid] = s2;
        __syncthreads();
        float var = (sb[0] + sb[1] + sb[2] + sb[3] + sb[4] + sb[5] + sb[6] + sb[7]) * (1.f / 256.f);
        __syncthreads();
        acc += d * rsqrtf(var + 1e-5f);
    }
    g_part[((size_t)(b * 32 + chunk)) * D_MODEL + c] = acc;
}

// ---------------- reduce partials, apply LN affine, compute heads -----------
__global__ void __launch_bounds__(256) final_k(
    const float* __restrict__ lnw, const float* __restrict__ lnb,
    const float* __restrict__ dirw, const float* __restrict__ dirb,
    const float* __restrict__ regw, const float* __restrict__ regb,
    float* __restrict__ out)
{
    __shared__ float hb[NB * D_MODEL];
    int t = threadIdx.x;
#pragma unroll
    for (int i = 0; i < (NB * D_MODEL) / 256; i++) {
        int idx = t + i * 256;
        int c = idx & 255;
        int bb = idx >> 8;
        float s = 0.f;
#pragma unroll
        for (int j = 0; j < 32; j++)
            s += g_part[((size_t)(bb * 32 + j)) * D_MODEL + c];
        hb[idx] = s * (1.f / 2048.f) * lnw[c] + lnb[c];
    }
    __syncthreads();
    if (t < NB) {
        float s = dirb[0];
        for (int c = 0; c < D_MODEL; c++) s += hb[t * D_MODEL + c] * dirw[c];
        out[t] = s;
    } else if (t < NB + NB * 3) {
        int q = t - NB;
        int bb = q / 3, j = q % 3;
        float s = regb[j];
        for (int c = 0; c < D_MODEL; c++) s += hb[bb * D_MODEL + c] * regw[c * 3 + j];
        out[NB + q] = s;
    }
}

// ---------------- launch ----------------------------------------------------
extern "C" void kernel_launch(void* const* d_in, const int* in_sizes, int n_in,
                              void* d_out, int out_size)
{
    const float* x    = (const float*)d_in[0];
    const float* inpw = (const float*)d_in[1];
    const float* inpb = (const float*)d_in[2];
    const float* ipw  = (const float*)d_in[3];
    const float* cw   = (const float*)d_in[4];
    const float* cb   = (const float*)d_in[5];
    const float* dtb  = (const float*)d_in[6];
    const float* alog = (const float*)d_in[7];
    const float* Dp   = (const float*)d_in[8];
    const float* rmsw = (const float*)d_in[9];
    const float* opw  = (const float*)d_in[10];
    const float* lnw  = (const float*)d_in[11];
    const float* lnb  = (const float*)d_in[12];
    const float* dirw = (const float*)d_in[13];
    const float* dirb = (const float*)d_in[14];
    const float* regw = (const float*)d_in[15];
    const float* regb = (const float*)d_in[16];
    float* out = (float*)d_out;

    void *ph_, *pzx_, *py_, *pw_;
    cudaGetSymbolAddress(&ph_,  g_h);
    cudaGetSymbolAddress(&pzx_, g_zx);
    cudaGetSymbolAddress(&py_,  g_y);
    cudaGetSymbolAddress(&pw_,  g_wr);
    float* ph  = (float*)ph_;
    float* pzx = (float*)pzx_;
    float* py  = (float*)py_;
    float* pwr = (float*)pw_;

    cudaFuncSetAttribute(scan_k, cudaFuncAttributeMaxDynamicSharedMemorySize,
                         SCAN_SMEM_BYTES);

    // pre-round weights (tf32) into g_wr — same stream, ordered before gemms
    roundw_k<<<((IPW_ELEMS + OPW_ELEMS) / 4 + 255) / 256, 256>>>(ipw, opw);

    // h = x @ inp_w + inp_b            [32768 x 256, K=46]  (fp32, tiny)
    sgemm_k<<<dim3(D_MODEL / 64, BL / 64), 128>>>(x, inpw, inpb, ph, BL, D_MODEL, NF, 0);

    const int convdt_threads = (BL / 8) * (CONV_DIM / 4) + BL * NHEADS;

    for (int i = 0; i < N_LAYERS; i++) {
        // zxbcdt = h @ in_proj_w       [32768 x 1160, K=256]  (B pre-rounded)
        tf32gemm_k<<<dim3((D_IN_PROJ + 63) / 64, BL / 128), 256>>>(
            ph, pwr + (size_t)i * D_MODEL * D_IN_PROJ, pzx,
            BL, D_IN_PROJ, D_MODEL, 0);
        // conv + silu (tf32-rounded, register-shifted) + (dtA, dt) precompute
        convdt_k<<<(convdt_threads + 255) / 256, 256>>>(
            cw + (size_t)i * CONV_DIM * 4, cb + (size_t)i * CONV_DIM,
            dtb + i * NHEADS, alog + i * NHEADS);
        // chunked SSD scan (+ D*x skip), CHUNK=64, single-pass tf32
        scan_k<<<NB * NHEADS, 256, SCAN_SMEM_BYTES>>>(Dp + i * NHEADS);
        // y = rmsnorm(y * silu(z)) * rms_w  (warp-per-row, fused)
        gate_rms_k<<<BL / 8, 256>>>(rmsw + (size_t)i * D_INNER);
        // h += y @ out_proj_w          [32768 x 256, K=512]  (B pre-rounded)
        tf32gemm_k<<<dim3(D_MODEL / 64, BL / 128), 256>>>(
            py, pwr + IPW_ELEMS + (size_t)i * D_INNER * D_MODEL, ph,
            BL, D_MODEL, D_INNER, 1);
    }

    ln_part_k<<<dim3(NB, 32), 256>>>();
    final_k<<<1, 256>>>(lnw, lnb, dirw, dirb, regw, regb, out);
}

// round 17
// speedup vs baseline: 1.0699x; 1.0147x over previous
#include <cuda_runtime.h>
#include <cstdint>

#define NB 16
#define NL 2048
#define NF 46
#define D_MODEL 256
#define D_INNER 512
#define D_STATE 64
#define NHEADS 8
#define HEADDIM 64
#define CONV_DIM 640
#define D_IN_PROJ 1160
#define N_LAYERS 4
#define BL (NB*NL)
#define CHUNK 64
#define NCHUNK (NL/CHUNK)

#define IPW_ELEMS (N_LAYERS * D_MODEL * D_IN_PROJ)   // 1,187,840
#define OPW_ELEMS (N_LAYERS * D_INNER * D_MODEL)     //   524,288

// ---------------- scratch (static device globals; no runtime allocation) ----
__device__ float g_h[(size_t)BL * D_MODEL];      // residual stream
__device__ float g_zx[(size_t)BL * D_IN_PROJ];   // in_proj output
__device__ float g_xc[(size_t)BL * CONV_DIM];    // conv+silu output (tf32-rounded)
__device__ float g_sd[(size_t)BL * NHEADS * 2];  // (dtA, dt) pairs, [b*8+h][l]
__device__ float g_y[(size_t)BL * D_INNER];      // scan output / gated-norm
__device__ float g_part[NB * 32 * D_MODEL];      // LN partial sums
__device__ float g_wr[IPW_ELEMS + OPW_ELEMS];    // tf32-pre-rounded weights

// ---------------- tf32 / cp.async helpers ------------------------------------
__device__ __forceinline__ uint32_t to_tf32(float x) {
    uint32_t r;
    asm("cvt.rna.tf32.f32 %0, %1;" : "=r"(r) : "f"(x));
    return r;
}
__device__ __forceinline__ float tf32r(float x) {
    return __uint_as_float(to_tf32(x));
}
__device__ __forceinline__ void cpa16(void* dst, const void* src) {
    uint32_t d = (uint32_t)__cvta_generic_to_shared(dst);
    asm volatile("cp.async.cg.shared.global [%0], [%1], 16;" :: "r"(d), "l"(src));
}
__device__ __forceinline__ void cpa16z(void* dst, const void* src, int bytes) {
    uint32_t d = (uint32_t)__cvta_generic_to_shared(dst);
    asm volatile("cp.async.cg.shared.global [%0], [%1], 16, %2;"
                 :: "r"(d), "l"(src), "r"(bytes));
}
__device__ __forceinline__ void cpa_commit() { asm volatile("cp.async.commit_group;"); }
__device__ __forceinline__ void cpa_wait0()  { asm volatile("cp.async.wait_group 0;"); }
__device__ __forceinline__ void cpa_wait1()  { asm volatile("cp.async.wait_group 1;"); }

__device__ __forceinline__ void mma_tf32(float c[4], const uint32_t a[4], const uint32_t b[2]) {
    asm volatile(
        "mma.sync.aligned.m16n8k8.row.col.f32.tf32.tf32.f32 "
        "{%0,%1,%2,%3}, {%4,%5,%6,%7}, {%8,%9}, {%0,%1,%2,%3};"
        : "+f"(c[0]), "+f"(c[1]), "+f"(c[2]), "+f"(c[3])
        : "r"(a[0]), "r"(a[1]), "r"(a[2]), "r"(a[3]), "r"(b[0]), "r"(b[1]));
}
// single-pass mma from pre-rounded fp32 smem values
__device__ __forceinline__ void mma1s(float c[4], const float a[4], const float b[2]) {
    uint32_t A[4] = {__float_as_uint(a[0]), __float_as_uint(a[1]),
                     __float_as_uint(a[2]), __float_as_uint(a[3])};
    uint32_t B[2] = {__float_as_uint(b[0]), __float_as_uint(b[1])};
    mma_tf32(c, A, B);
}

// ---------------- weight pre-round: g_wr = tf32(ipw ++ opw) ------------------
__global__ void __launch_bounds__(256) roundw_k(
    const float* __restrict__ ipw, const float* __restrict__ opw)
{
    int i4 = blockIdx.x * 256 + threadIdx.x;
    const int totq = (IPW_ELEMS + OPW_ELEMS) / 4;
    if (i4 >= totq) return;
    int e = i4 * 4;
    float4 v = (e < IPW_ELEMS) ? *(const float4*)(ipw + e)
                               : *(const float4*)(opw + (e - IPW_ELEMS));
    float4 o;
    o.x = tf32r(v.x); o.y = tf32r(v.y); o.z = tf32r(v.z); o.w = tf32r(v.w);
    *(float4*)(g_wr + e) = o;
}

// ---------------- tf32 tensor-core GEMM: BM=128,BN=64,BK=32 ------------------
// B must be tf32-pre-rounded (bit-loaded); A is cvt.rna'd in-loop.
// 3-stage pipeline, dynamic smem. TAIL-RACE FIX: when no real stage remains,
// commit an EMPTY group so wait_group(1) provably completes stage kt (the
// old protocol left stage KT-1 as the single newest outstanding group, which
// wait_group(1) does NOT wait for — a latent, timing-dependent race).
#define GA_ST 36
#define GB_ST 72
#define GEMM_A_STAGE (128 * GA_ST)                  // 4608 floats
#define GEMM_B_STAGE (32 * GB_ST)                   // 2304 floats
#define GEMM_SMEM_BYTES ((3 * (GEMM_A_STAGE + GEMM_B_STAGE)) * 4)   // 82944

__global__ void __launch_bounds__(256) tf32gemm_k(
    const float* __restrict__ A, const float* __restrict__ B,
    float* __restrict__ C, int M, int N, int K, int acc_flag)
{
    extern __shared__ __align__(16) float gsm[];
    float* Abase = gsm;                         // [3][128][36]
    float* Bbase = gsm + 3 * GEMM_A_STAGE;      // [3][32][72]

    const int tid  = threadIdx.x;
    const int bm   = blockIdx.y * 128;
    const int bn   = blockIdx.x * 64;
    const int warp = tid >> 5, lane = tid & 31;
    const int wm   = (warp >> 1) * 32;
    const int wn   = (warp & 1) * 32;
    const int g    = lane >> 2;
    const int tg   = lane & 3;

    float acc[2][4][4];
#pragma unroll
    for (int mt = 0; mt < 2; mt++)
#pragma unroll
        for (int nt = 0; nt < 4; nt++)
#pragma unroll
            for (int i = 0; i < 4; i++) acc[mt][nt][i] = 0.f;

    const int KT = K >> 5;

    auto load_stage = [&](int s, int k0) {
        float* as = Abase + s * GEMM_A_STAGE;
        float* bs = Bbase + s * GEMM_B_STAGE;
#pragma unroll
        for (int i = 0; i < 4; i++) {           // A: 1024 float4/stage
            int slot = tid + i * 256;
            int m = slot >> 3, kq = (slot & 7) * 4;
            cpa16(as + m * GA_ST + kq, A + (size_t)(bm + m) * K + k0 + kq);
        }
#pragma unroll
        for (int i = 0; i < 2; i++) {           // B: 512 float4/stage
            int slot = tid + i * 256;
            int bk = slot >> 4, bq = (slot & 15) * 4;
            int n = bn + bq;
            int nc = n < N - 4 ? n : N - 4;
            int bytes = (n < N) ? ((N - n) * 4 < 16 ? (N - n) * 4 : 16) : 0;
            cpa16z(bs + bk * GB_ST + bq, B + (size_t)(k0 + bk) * N + nc, bytes);
        }
        cpa_commit();
    };

    load_stage(0, 0);
    if (KT > 1) load_stage(1, 32);
    else cpa_commit();                           // keep 2 groups outstanding

    for (int kt = 0; kt < KT; kt++) {
        cpa_wait1();                             // with 2 outstanding: stage kt done
        __syncthreads();
        if (kt + 2 < KT) load_stage((kt + 2) % 3, (kt + 2) * 32);
        else cpa_commit();                       // empty group: keeps protocol sound
        const int s = kt % 3;
        const float* as = Abase + s * GEMM_A_STAGE;
        const float* bs = Bbase + s * GEMM_B_STAGE;
#pragma unroll
        for (int ks = 0; ks < 4; ks++) {
            uint32_t af[2][4];
#pragma unroll
            for (int mt = 0; mt < 2; mt++) {
                int r = wm + mt * 16 + g;
                int c = ks * 8 + tg;
                af[mt][0] = to_tf32(as[r * GA_ST + c]);
                af[mt][1] = to_tf32(as[(r + 8) * GA_ST + c]);
                af[mt][2] = to_tf32(as[r * GA_ST + c + 4]);
                af[mt][3] = to_tf32(as[(r + 8) * GA_ST + c + 4]);
            }
            uint32_t bf[4][2];
#pragma unroll
            for (int nt = 0; nt < 4; nt++) {
                int col = wn + nt * 8 + g;
                bf[nt][0] = __float_as_uint(bs[(ks * 8 + tg) * GB_ST + col]);
                bf[nt][1] = __float_as_uint(bs[(ks * 8 + tg + 4) * GB_ST + col]);
            }
#pragma unroll
            for (int mt = 0; mt < 2; mt++)
#pragma unroll
                for (int nt = 0; nt < 4; nt++)
                    mma_tf32(acc[mt][nt], af[mt], bf[nt]);
        }
        __syncthreads();                         // all reads of stage s done
    }

#pragma unroll
    for (int mt = 0; mt < 2; mt++) {
        int r0 = bm + wm + mt * 16 + g;
#pragma unroll
        for (int nt = 0; nt < 4; nt++) {
            int col = bn + wn + nt * 8 + 2 * tg;
            if (col < N) {
                size_t o0 = (size_t)r0 * N + col;
                size_t o1 = (size_t)(r0 + 8) * N + col;
                if (acc_flag) {
                    C[o0]     += acc[mt][nt][0];
                    C[o0 + 1] += acc[mt][nt][1];
                    C[o1]     += acc[mt][nt][2];
                    C[o1 + 1] += acc[mt][nt][3];
                } else {
                    C[o0]     = acc[mt][nt][0];
                    C[o0 + 1] = acc[mt][nt][1];
                    C[o1]     = acc[mt][nt][2];
                    C[o1 + 1] = acc[mt][nt][3];
                }
            }
        }
    }
}

// ---------------- fp32 tiled SGEMM (tiny K=46 input GEMM) -------------------
__global__ void __launch_bounds__(128) sgemm_k(
    const float* __restrict__ A, const float* __restrict__ B,
    const float* __restrict__ bias, float* __restrict__ C,
    int M, int N, int K, int acc_flag)
{
    __shared__ __align__(16) float As[16][68];
    __shared__ __align__(16) float Bs[16][64];
    const int bm = blockIdx.y * 64;
    const int bn = blockIdx.x * 64;
    const int tid = threadIdx.x;
    const int tx = tid & 7;
    const int ty = tid >> 3;
    const int aRow = tid >> 4;
    const int aCol = tid & 15;
    const int bRow = tid >> 6;
    const int bCol = tid & 63;

    float acc[4][8];
#pragma unroll
    for (int i = 0; i < 4; i++)
#pragma unroll
        for (int j = 0; j < 8; j++) acc[i][j] = 0.f;

    for (int k0 = 0; k0 < K; k0 += 16) {
#pragma unroll
        for (int i = 0; i < 8; i++) {
            int m = bm + aRow + 8 * i;
            int k = k0 + aCol;
            As[aCol][aRow + 8 * i] = (k < K) ? A[(size_t)m * K + k] : 0.f;
        }
#pragma unroll
        for (int i = 0; i < 8; i++) {
            int k = k0 + bRow + 2 * i;
            int n = bn + bCol;
            Bs[bRow + 2 * i][bCol] = (k < K && n < N) ? B[(size_t)k * N + n] : 0.f;
        }
        __syncthreads();
#pragma unroll
        for (int k = 0; k < 16; k++) {
            float4 a4  = *(const float4*)&As[k][ty * 4];
            float4 b4a = *(const float4*)&Bs[k][tx * 8];
            float4 b4b = *(const float4*)&Bs[k][tx * 8 + 4];
            float a[4]  = {a4.x, a4.y, a4.z, a4.w};
            float bb[8] = {b4a.x, b4a.y, b4a.z, b4a.w, b4b.x, b4b.y, b4b.z, b4b.w};
#pragma unroll
            for (int i = 0; i < 4; i++)
#pragma unroll
                for (int j = 0; j < 8; j++)
                    acc[i][j] = fmaf(a[i], bb[j], acc[i][j]);
        }
        __syncthreads();
    }
#pragma unroll
    for (int i = 0; i < 4; i++) {
        int m = bm + ty * 4 + i;
#pragma unroll
        for (int j = 0; j < 8; j++) {
            int n = bn + tx * 8 + j;
            if (n < N) {
                float v = acc[i][j];
                if (bias) v += bias[n];
                size_t off = (size_t)m * N + n;
                if (acc_flag) v += C[off];
                C[off] = v;
            }
        }
    }
}

// -------- fused: depthwise conv(k=4)+bias+silu v2 (8 tok x 4 ch / thread) ---
__global__ void __launch_bounds__(256) convdt_k(
    const float* __restrict__ cw, const float* __restrict__ cb,
    const float* __restrict__ dtb, const float* __restrict__ Alog)
{
    const int CG = CONV_DIM / 4;              // 160 channel-groups
    const int convN = (BL / 8) * CG;          // 655,360 (multiple of 256)
    int idx = blockIdx.x * 256 + threadIdx.x;
    if (idx < convN) {
        int blg = idx / CG, cg = idx - blg * CG;
        int bl0 = blg * 8;                    // 8 tokens, never crosses batch
        int l0  = bl0 & (NL - 1);
        int c   = cg * 4;
        const float* base = g_zx + (size_t)bl0 * D_IN_PROJ + 512 + c;

        float4 v[11];
#pragma unroll
        for (int i = 0; i < 11; i++) {
            int off = i - 3;
            if (l0 + off >= 0)
                v[i] = *(const float4*)(base + (ptrdiff_t)off * D_IN_PROJ);
            else
                v[i] = make_float4(0.f, 0.f, 0.f, 0.f);
        }
        float4 w0 = *(const float4*)(cw + (size_t)(c + 0) * 4);
        float4 w1 = *(const float4*)(cw + (size_t)(c + 1) * 4);
        float4 w2 = *(const float4*)(cw + (size_t)(c + 2) * 4);
        float4 w3 = *(const float4*)(cw + (size_t)(c + 3) * 4);
        float4 bb = *(const float4*)(cb + c);
        const float wk0[4] = {w0.x, w0.y, w0.z, w0.w};
        const float wk1[4] = {w1.x, w1.y, w1.z, w1.w};
        const float wk2[4] = {w2.x, w2.y, w2.z, w2.w};
        const float wk3[4] = {w3.x, w3.y, w3.z, w3.w};

        float* outp = g_xc + (size_t)bl0 * CONV_DIM + c;
#pragma unroll
        for (int i = 0; i < 8; i++) {
            float a0 = bb.x, a1 = bb.y, a2 = bb.z, a3 = bb.w;
#pragma unroll
            for (int k = 0; k < 4; k++) {
                a0 = fmaf(v[i + k].x, wk0[k], a0);
                a1 = fmaf(v[i + k].y, wk1[k], a1);
                a2 = fmaf(v[i + k].z, wk2[k], a2);
                a3 = fmaf(v[i + k].w, wk3[k], a3);
            }
            float4 o;
            o.x = tf32r(a0 / (1.f + __expf(-a0)));
            o.y = tf32r(a1 / (1.f + __expf(-a1)));
            o.z = tf32r(a2 / (1.f + __expf(-a2)));
            o.w = tf32r(a3 / (1.f + __expf(-a3)));
            *(float4*)(outp + (size_t)i * CONV_DIM) = o;
        }
    } else {
        int j = idx - convN;
        if (j < BL * NHEADS) {
            int l  = j & (NL - 1);
            int bh = j >> 11;
            int b  = bh >> 3;
            int h  = bh & 7;
            float v = g_zx[((size_t)(b * NL + l)) * D_IN_PROJ + 1152 + h] + dtb[h];
            float dt = (v > 20.f) ? v : log1pf(expf(v));
            float dtA = dt * (-__expf(Alog[h]));
            ((float2*)g_sd)[j] = make_float2(dtA, dt);
        }
    }
}

// ---------------- scan v8: chunked SSD, CHUNK=64, triangle skips -------------
// (uses cp.async.wait_group 0 — waits for ALL groups, no tail race)
#define OFF_F    0                       // stage [2 buf][3 tile][64][68] (X,B,C)
#define SZ_TILE  4352                    // 64*68
#define SZ_FBUF  (3*SZ_TILE)             // 13056
#define OFF_W    (2*SZ_FBUF)             // W [64][68]
#define OFF_BW   (OFF_W + SZ_TILE)       // Bw [64][68]
#define OFF_S    (OFF_BW + SZ_TILE)      // S mirror [64][68]
#define OFF_SD   (OFF_S + SZ_TILE)       // (dtA,dt) [2 buf][64 float2]
#define OFF_SC   (OFF_SD + 256)          // s_s[64],s_dt[64],s_wq[64],s_el[64],ptot
#define SCAN_SMEM_FLOATS (OFF_SC + 260)
#define SCAN_SMEM_BYTES  (SCAN_SMEM_FLOATS * 4)

__global__ void __launch_bounds__(256) scan_k(const float* __restrict__ Dp)
{
    extern __shared__ __align__(16) float dsm[];

    const int bh = blockIdx.x;
    const int b = bh >> 3, h = bh & 7;
    const int t = threadIdx.x;
    const int w = t >> 5, lane = t & 31;
    const int g = lane >> 2, tg = lane & 3;
    const float Dh = Dp[h];

    const float* xcb = g_xc + (size_t)b * NL * CONV_DIM;
    const float* sdp = g_sd + (size_t)bh * NL * 2;

    float* s_s  = dsm + OFF_SC;
    float* s_dt = dsm + OFF_SC + 64;
    float* s_wq = dsm + OFF_SC + 128;
    float* s_el = dsm + OFF_SC + 192;

    for (int i = t; i < SZ_TILE; i += 256) dsm[OFF_S + i] = 0.f;

    float Sreg[4][4];
#pragma unroll
    for (int i = 0; i < 4; i++)
#pragma unroll
        for (int r = 0; r < 4; r++) Sreg[i][r] = 0.f;

    auto stage = [&](int buf, int l0) {
        float* fb = dsm + OFF_F + buf * SZ_FBUF;
#pragma unroll
        for (int i = 0; i < 12; i++) {
            int slot = t + i * 256;
            int tile = slot >> 10;
            int rc = slot & 1023;
            int row = rc >> 4, c4 = (rc & 15) * 4;
            const float* src = xcb + (size_t)(l0 + row) * CONV_DIM;
            const int goff = (tile == 0) ? h * HEADDIM : (tile == 1 ? 512 : 576);
            cpa16(fb + tile * SZ_TILE + row * 68 + c4, src + goff + c4);
        }
        if (t < 32)
            cpa16(dsm + OFF_SD + buf * 128 + t * 4, sdp + (size_t)l0 * 2 + t * 4);
        cpa_commit();
    };

    stage(0, 0);

    const int mb = (w & 3) * 16, c0 = (w >> 2) * 32;
    const int pm = mb, nh = c0;

    for (int ch = 0; ch < NCHUNK; ch++) {
        const int buf = ch & 1;
        const int l0 = ch * CHUNK;
        const float* fX = dsm + OFF_F + buf * SZ_FBUF;
        const float* fB = fX + SZ_TILE;
        const float* fC = fB + SZ_TILE;

        cpa_wait0();
        __syncthreads();

        if (ch + 1 < NCHUNK) stage(buf ^ 1, l0 + CHUNK);

        if (w == 0) {
            const float2* sd2 = (const float2*)(dsm + OFF_SD + buf * 128);
            float2 ua = sd2[2 * lane];
            float2 ub = sd2[2 * lane + 1];
            float ps = ua.x + ub.x;
            float sc_ = ps;
#pragma unroll
            for (int o = 1; o < 32; o <<= 1) {
                float v = __shfl_up_sync(0xffffffffu, sc_, o);
                if (lane >= o) sc_ += v;
            }
            float stot = __shfl_sync(0xffffffffu, sc_, 31);
            float s1 = sc_;
            float s0 = sc_ - ub.x;
            s_s[2 * lane]      = s0;
            s_s[2 * lane + 1]  = s1;
            s_dt[2 * lane]     = ua.y;
            s_dt[2 * lane + 1] = ub.y;
            s_wq[2 * lane]     = __expf(stot - s0) * ua.y;
            s_wq[2 * lane + 1] = __expf(stot - s1) * ub.y;
            s_el[2 * lane]     = __expf(s0);
            s_el[2 * lane + 1] = __expf(s1);
            if (lane == 31) dsm[OFF_SC + 256] = __expf(stot);
        }

        float Gacc[4][4] = {{0,0,0,0},{0,0,0,0},{0,0,0,0},{0,0,0,0}};
        if (mb + 15 >= c0) {
#pragma unroll
            for (int k8 = 0; k8 < 8; k8++) {
                int kc = k8 * 8;
                float a[4];
                a[0] = fC[(mb + g) * 68 + kc + tg];
                a[1] = fC[(mb + g + 8) * 68 + kc + tg];
                a[2] = fC[(mb + g) * 68 + kc + tg + 4];
                a[3] = fC[(mb + g + 8) * 68 + kc + tg + 4];
#pragma unroll
                for (int n8 = 0; n8 < 4; n8++) {
                    if (mb + 15 >= c0 + n8 * 8) {
                        float bv[2];
                        bv[0] = fB[(c0 + n8 * 8 + g) * 68 + kc + tg];
                        bv[1] = fB[(c0 + n8 * 8 + g) * 68 + kc + tg + 4];
                        mma1s(Gacc[n8], a, bv);
                    }
                }
            }
        }
        __syncthreads();

        {
            int la = mb + g, lb = la + 8;
#pragma unroll
            for (int n8 = 0; n8 < 4; n8++) {
                int ja = c0 + n8 * 8 + 2 * tg, jb2 = ja + 1;
                float w0_ = (la >= ja)  ? Gacc[n8][0] * __expf(s_s[la] - s_s[ja])  * s_dt[ja]  : 0.f;
                float w1_ = (la >= jb2) ? Gacc[n8][1] * __expf(s_s[la] - s_s[jb2]) * s_dt[jb2] : 0.f;
                float w2_ = (lb >= ja)  ? Gacc[n8][2] * __expf(s_s[lb] - s_s[ja])  * s_dt[ja]  : 0.f;
                float w3_ = (lb >= jb2) ? Gacc[n8][3] * __expf(s_s[lb] - s_s[jb2]) * s_dt[jb2] : 0.f;
                dsm[OFF_W + la * 68 + ja]  = tf32r(w0_);
                dsm[OFF_W + la * 68 + jb2] = tf32r(w1_);
                dsm[OFF_W + lb * 68 + ja]  = tf32r(w2_);
                dsm[OFF_W + lb * 68 + jb2] = tf32r(w3_);
            }
        }
#pragma unroll
        for (int i = 0; i < 16; i++) {
            int idx = t + i * 256;
            int r = idx >> 6, c = idx & 63;
            dsm[OFF_BW + r * 68 + c] = tf32r(s_wq[r] * fB[r * 68 + c]);
        }
        __syncthreads();

        float Y[4][4] = {{0,0,0,0},{0,0,0,0},{0,0,0,0},{0,0,0,0}};
#pragma unroll
        for (int k8 = 0; k8 < 8; k8++) {
            int kc = k8 * 8;
            if (kc > mb + 15) break;
            float a[4];
            a[0] = dsm[OFF_W + (mb + g) * 68 + kc + tg];
            a[1] = dsm[OFF_W + (mb + g + 8) * 68 + kc + tg];
            a[2] = dsm[OFF_W + (mb + g) * 68 + kc + tg + 4];
            a[3] = dsm[OFF_W + (mb + g + 8) * 68 + kc + tg + 4];
#pragma unroll
            for (int n8 = 0; n8 < 4; n8++) {
                int p = c0 + n8 * 8 + g;
                float bv[2];
                bv[0] = fX[(kc + tg) * 68 + p];
                bv[1] = fX[(kc + tg + 4) * 68 + p];
                mma1s(Y[n8], a, bv);
            }
        }
        float Y3[4][4] = {{0,0,0,0},{0,0,0,0},{0,0,0,0},{0,0,0,0}};
#pragma unroll
        for (int k8 = 0; k8 < 8; k8++) {
            int kc = k8 * 8;
            float a[4];
            a[0] = fC[(mb + g) * 68 + kc + tg];
            a[1] = fC[(mb + g + 8) * 68 + kc + tg];
            a[2] = fC[(mb + g) * 68 + kc + tg + 4];
            a[3] = fC[(mb + g + 8) * 68 + kc + tg + 4];
#pragma unroll
            for (int n8 = 0; n8 < 4; n8++) {
                int p = c0 + n8 * 8 + g;
                float bv[2];
                bv[0] = dsm[OFF_S + p * 68 + kc + tg];
                bv[1] = dsm[OFF_S + p * 68 + kc + tg + 4];
                mma1s(Y3[n8], a, bv);
            }
        }
        {
            float e0 = s_el[mb + g], e1 = s_el[mb + g + 8];
#pragma unroll
            for (int n8 = 0; n8 < 4; n8++) {
                Y[n8][0] = fmaf(e0, Y3[n8][0], Y[n8][0]);
                Y[n8][1] = fmaf(e0, Y3[n8][1], Y[n8][1]);
                Y[n8][2] = fmaf(e1, Y3[n8][2], Y[n8][2]);
                Y[n8][3] = fmaf(e1, Y3[n8][3], Y[n8][3]);
            }
        }
        {
            int la = mb + g, lb = la + 8;
            float* ya_ = g_y + ((size_t)(b * NL + l0 + la)) * D_INNER + h * HEADDIM;
            float* yb_ = g_y + ((size_t)(b * NL + l0 + lb)) * D_INNER + h * HEADDIM;
#pragma unroll
            for (int n8 = 0; n8 < 4; n8++) {
                int p0 = c0 + n8 * 8 + 2 * tg;
                ya_[p0]     = Y[n8][0] + Dh * fX[la * 68 + p0];
                ya_[p0 + 1] = Y[n8][1] + Dh * fX[la * 68 + p0 + 1];
                yb_[p0]     = Y[n8][2] + Dh * fX[lb * 68 + p0];
                yb_[p0 + 1] = Y[n8][3] + Dh * fX[lb * 68 + p0 + 1];
            }
        }
        {
            float pt = dsm[OFF_SC + 256];
#pragma unroll
            for (int n8 = 0; n8 < 4; n8++)
#pragma unroll
                for (int r = 0; r < 4; r++) Sreg[n8][r] *= pt;
#pragma unroll
            for (int k8 = 0; k8 < 8; k8++) {
                int kc = k8 * 8;
                float a[4];
                a[0] = fX[(kc + tg) * 68 + pm + g];
                a[1] = fX[(kc + tg) * 68 + pm + g + 8];
                a[2] = fX[(kc + tg + 4) * 68 + pm + g];
                a[3] = fX[(kc + tg + 4) * 68 + pm + g + 8];
#pragma unroll
                for (int n8 = 0; n8 < 4; n8++) {
                    int n = nh + n8 * 8 + g;
                    float bv[2];
                    bv[0] = dsm[OFF_BW + (kc + tg) * 68 + n];
                    bv[1] = dsm[OFF_BW + (kc + tg + 4) * 68 + n];
                    mma1s(Sreg[n8], a, bv);
                }
            }
        }
        __syncthreads();
#pragma unroll
        for (int n8 = 0; n8 < 4; n8++) {
            int n0 = nh + n8 * 8 + 2 * tg;
            dsm[OFF_S + (pm + g) * 68 + n0]         = tf32r(Sreg[n8][0]);
            dsm[OFF_S + (pm + g) * 68 + n0 + 1]     = tf32r(Sreg[n8][1]);
            dsm[OFF_S + (pm + g + 8) * 68 + n0]     = tf32r(Sreg[n8][2]);
            dsm[OFF_S + (pm + g + 8) * 68 + n0 + 1] = tf32r(Sreg[n8][3]);
        }
    }
}

// ------ fused gate + rms, warp-per-row: y = rmsnorm(y*silu(z)) * rms_w ------
__global__ void __launch_bounds__(256) gate_rms_k(const float* __restrict__ rmsw)
{
    int w = threadIdx.x >> 5, lane = threadIdx.x & 31;
    size_t row = (size_t)blockIdx.x * 8 + w;
    float4* y4 = (float4*)(g_y + row * D_INNER);
    const float4* z4 = (const float4*)(g_zx + row * D_IN_PROJ);
    float4 gv[4];
    float ss = 0.f;
#pragma unroll
    for (int i = 0; i < 4; i++) {
        float4 yv = y4[lane + i * 32];
        float4 zv = z4[lane + i * 32];
        float4 g;
        g.x = yv.x * (zv.x / (1.f + __expf(-zv.x)));
        g.y = yv.y * (zv.y / (1.f + __expf(-zv.y)));
        g.z = yv.z * (zv.z / (1.f + __expf(-zv.z)));
        g.w = yv.w * (zv.w / (1.f + __expf(-zv.w)));
        gv[i] = g;
        ss += g.x * g.x + g.y * g.y + g.z * g.z + g.w * g.w;
    }
#pragma unroll
    for (int o = 16; o > 0; o >>= 1) ss += __shfl_xor_sync(0xffffffffu, ss, o);
    float sc = rsqrtf(ss * (1.f / 512.f) + 1e-5f);
#pragma unroll
    for (int i = 0; i < 4; i++) {
        float4 wv = ((const float4*)rmsw)[lane + i * 32];
        float4 o;
        o.x = gv[i].x * sc * wv.x;
        o.y = gv[i].y * sc * wv.y;
        o.z = gv[i].z * sc * wv.z;
        o.w = gv[i].w * sc * wv.w;
        y4[lane + i * 32] = o;
    }
}

// ---------------- final LayerNorm (per row) + partial mean over l -----------
__global__ void __launch_bounds__(256) ln_part_k()
{
    __shared__ float sb[8];
    int b = blockIdx.x;
    int chunk = blockIdx.y;
    int c = threadIdx.x;
    int lane = c & 31, wid = c >> 5;
    float acc = 0.f;
    for (int i = 0; i < 64; i++) {
        int l = chunk * 64 + i;
        float v = g_h[((size_t)(b * NL + l)) * D_MODEL + c];
        float s = v;
#pragma unroll
        for (int o = 16; o > 0; o >>= 1) s += __shfl_xor_sync(0xffffffffu, s, o);
        if (lane == 0) sb[wid] = s;
        __syncthreads();
        float tot = sb[0] + sb[1] + sb[2] + sb[3] + sb[4] + sb[5] + sb[6] + sb[7];
        __syncthreads();
        float mu = tot * (1.f / 256.f);
        float d = v - mu;
        float s2 = d * d;
#pragma unroll
        for (int o = 16; o > 0; o >>= 1) s2 += __shfl_xor_sync(0xffffffffu, s2, o);
        if (lane == 0) sb[wid] = s2;
        __syncthreads();
        float var = (sb[0] + sb[1] + sb[2] + sb[3] + sb[4] + sb[5] + sb[6] + sb[7]) * (1.f / 256.f);
        __syncthreads();
        acc += d * rsqrtf(var + 1e-5f);
    }
    g_part[((size_t)(b * 32 + chunk)) * D_MODEL + c] = acc;
}

// ---------------- reduce partials, apply LN affine, compute heads -----------
__global__ void __launch_bounds__(256) final_k(
    const float* __restrict__ lnw, const float* __restrict__ lnb,
    const float* __restrict__ dirw, const float* __restrict__ dirb,
    const float* __restrict__ regw, const float* __restrict__ regb,
    float* __restrict__ out)
{
    __shared__ float hb[NB * D_MODEL];
    int t = threadIdx.x;
#pragma unroll
    for (int i = 0; i < (NB * D_MODEL) / 256; i++) {
        int idx = t + i * 256;
        int c = idx & 255;
        int bb = idx >> 8;
        float s = 0.f;
#pragma unroll
        for (int j = 0; j < 32; j++)
            s += g_part[((size_t)(bb * 32 + j)) * D_MODEL + c];
        hb[idx] = s * (1.f / 2048.f) * lnw[c] + lnb[c];
    }
    __syncthreads();
    if (t < NB) {
        float s = dirb[0];
        for (int c = 0; c < D_MODEL; c++) s += hb[t * D_MODEL + c] * dirw[c];
        out[t] = s;
    } else if (t < NB + NB * 3) {
        int q = t - NB;
        int bb = q / 3, j = q % 3;
        float s = regb[j];
        for (int c = 0; c < D_MODEL; c++) s += hb[bb * D_MODEL + c] * regw[c * 3 + j];
        out[NB + q] = s;
    }
}

// ---------------- launch ----------------------------------------------------
extern "C" void kernel_launch(void* const* d_in, const int* in_sizes, int n_in,
                              void* d_out, int out_size)
{
    const float* x    = (const float*)d_in[0];
    const float* inpw = (const float*)d_in[1];
    const float* inpb = (const float*)d_in[2];
    const float* ipw  = (const float*)d_in[3];
    const float* cw   = (const float*)d_in[4];
    const float* cb   = (const float*)d_in[5];
    const float* dtb  = (const float*)d_in[6];
    const float* alog = (const float*)d_in[7];
    const float* Dp   = (const float*)d_in[8];
    const float* rmsw = (const float*)d_in[9];
    const float* opw  = (const float*)d_in[10];
    const float* lnw  = (const float*)d_in[11];
    const float* lnb  = (const float*)d_in[12];
    const float* dirw = (const float*)d_in[13];
    const float* dirb = (const float*)d_in[14];
    const float* regw = (const float*)d_in[15];
    const float* regb = (const float*)d_in[16];
    float* out = (float*)d_out;

    void *ph_, *pzx_, *py_, *pw_;
    cudaGetSymbolAddress(&ph_,  g_h);
    cudaGetSymbolAddress(&pzx_, g_zx);
    cudaGetSymbolAddress(&py_,  g_y);
    cudaGetSymbolAddress(&pw_,  g_wr);
    float* ph  = (float*)ph_;
    float* pzx = (float*)pzx_;
    float* py  = (float*)py_;
    float* pwr = (float*)pw_;

    cudaFuncSetAttribute(scan_k, cudaFuncAttributeMaxDynamicSharedMemorySize,
                         SCAN_SMEM_BYTES);
    cudaFuncSetAttribute(tf32gemm_k, cudaFuncAttributeMaxDynamicSharedMemorySize,
                         GEMM_SMEM_BYTES);

    // pre-round weights (tf32) into g_wr — same stream, ordered before gemms
    roundw_k<<<((IPW_ELEMS + OPW_ELEMS) / 4 + 255) / 256, 256>>>(ipw, opw);

    // h = x @ inp_w + inp_b            [32768 x 256, K=46]  (fp32, tiny)
    sgemm_k<<<dim3(D_MODEL / 64, BL / 64), 128>>>(x, inpw, inpb, ph, BL, D_MODEL, NF, 0);

    const int convdt_threads = (BL / 8) * (CONV_DIM / 4) + BL * NHEADS;

    for (int i = 0; i < N_LAYERS; i++) {
        // zxbcdt = h @ in_proj_w       [32768 x 1160, K=256]  (B pre-rounded, BK=32)
        tf32gemm_k<<<dim3((D_IN_PROJ + 63) / 64, BL / 128), 256, GEMM_SMEM_BYTES>>>(
            ph, pwr + (size_t)i * D_MODEL * D_IN_PROJ, pzx,
            BL, D_IN_PROJ, D_MODEL, 0);
        // conv + silu (tf32-rounded, register-shifted) + (dtA, dt) precompute
        convdt_k<<<(convdt_threads + 255) / 256, 256>>>(
            cw + (size_t)i * CONV_DIM * 4, cb + (size_t)i * CONV_DIM,
            dtb + i * NHEADS, alog + i * NHEADS);
        // chunked SSD scan (+ D*x skip), CHUNK=64, single-pass tf32
        scan_k<<<NB * NHEADS, 256, SCAN_SMEM_BYTES>>>(Dp + i * NHEADS);
        // y = rmsnorm(y * silu(z)) * rms_w  (warp-per-row, fused, fp32 store)
        gate_rms_k<<<BL / 8, 256>>>(rmsw + (size_t)i * D_INNER);
        // h += y @ out_proj_w          [32768 x 256, K=512]  (B pre-rounded, BK=32)
        tf32gemm_k<<<dim3(D_MODEL / 64, BL / 128), 256, GEMM_SMEM_BYTES>>>(
            py, pwr + IPW_ELEMS + (size_t)i * D_INNER * D_MODEL, ph,
            BL, D_MODEL, D_INNER, 1);
    }

    ln_part_k<<<dim3(NB, 32), 256>>>();
    final_k<<<1, 256>>>(lnw, lnb, dirw, dirb, regw, regb, out);
}